// round 1
// baseline (speedup 1.0000x reference)
#include <cuda_runtime.h>
#include <math.h>

// ---------------- problem constants ----------------
constexpr int N = 2048, E = 5, C = 2, W_IN = 256, W_OUT = 128, NUM_CLASS = 8, NT = 1024;
constexpr size_t NN = (size_t)N * (size_t)N;

// ---------------- scratch layout (floats) ----------------
constexpr size_t OFF_A     = 0;                                   // a [C,N,N]; later H2 [C,N,N]
constexpr size_t OFF_B     = OFF_A  + C * NN;                     // b [C,N,N]; later Hsum [N,N]
constexpr size_t OFF_A1    = OFF_B  + C * NN;                     // a1 [C,N,N]
constexpr size_t OFF_H     = OFF_A1 + C * NN;                     // H [C,N,N]
constexpr size_t OFF_CINV1 = OFF_H  + C * NN;                     // [C,N]
constexpr size_t OFF_CINV2 = OFF_CINV1 + (size_t)C * N;           // [C,N]
constexpr size_t OFF_CINVS = OFF_CINV2 + (size_t)C * N;           // [N]
constexpr size_t OFF_XW    = OFF_CINVS + N;                       // [N,128]
constexpr size_t OFF_XCAT  = OFF_XW   + (size_t)N * W_OUT;        // [N,256]
constexpr size_t OFF_XCW1  = OFF_XCAT + (size_t)N * (C * W_OUT);  // [N,128]
constexpr size_t OFF_XCW2  = OFF_XCW1 + (size_t)N * W_OUT;        // [N,256]
constexpr size_t OFF_XO    = OFF_XCW2 + (size_t)N * W_IN;         // [N,128]
constexpr size_t OFF_XR    = OFF_XO   + (size_t)N * W_OUT;        // [N,256]
constexpr size_t OFF_SW    = OFF_XR   + (size_t)N * W_IN;         // 30 softmax weights (pad 32)
constexpr size_t OFF_PARTR = OFF_SW + 32;                         // 512 partials
constexpr size_t OFF_PARTC = OFF_PARTR + 512;                     // 4 partials (pad 16)
constexpr size_t SCRATCH_FLOATS = OFF_PARTC + 16;

__device__ __align__(256) float g_scratch[SCRATCH_FLOATS];

// ---------------- softmax of the three [C,E] weights + write Ws outputs ----------------
__global__ void softmax_init_k(const float* __restrict__ w0a, const float* __restrict__ w0b,
                               const float* __restrict__ w1a, float* __restrict__ sw,
                               float* __restrict__ out) {
    int r = threadIdx.x;
    if (r < 3 * C) {
        int t = r >> 1, c = r & 1;
        const float* src = (t == 0) ? w0a : (t == 1) ? w0b : w1a;
        src += c * E;
        float v[E]; float m = -1e30f;
        #pragma unroll
        for (int e = 0; e < E; e++) { v[e] = src[e]; m = fmaxf(m, v[e]); }
        float s = 0.f;
        #pragma unroll
        for (int e = 0; e < E; e++) { v[e] = expf(v[e] - m); s += v[e]; }
        #pragma unroll
        for (int e = 0; e < E; e++) {
            float q = v[e] / s;
            sw[t * (C * E) + c * E + e] = q;
            out[1 + NT * NUM_CLASS + t * (C * E) + c * E + e] = q;
        }
    }
}

// ---------------- fused GT conv: a,b,a1 = einsum(softmax(w), A) in one pass over A ----------------
__global__ void gtconv_k(const float* __restrict__ A, const float* __restrict__ sw,
                         float* __restrict__ pa, float* __restrict__ pb, float* __restrict__ pa1) {
    size_t idx = (size_t)blockIdx.x * blockDim.x + threadIdx.x;
    if (idx >= NN) return;
    float av[E];
    #pragma unroll
    for (int e = 0; e < E; e++) av[e] = A[idx * E + e];
    #pragma unroll
    for (int c = 0; c < C; c++) {
        float sa = 0.f, sb = 0.f, s1 = 0.f;
        #pragma unroll
        for (int e = 0; e < E; e++) {
            sa = fmaf(sw[c * E + e],             av[e], sa);
            sb = fmaf(sw[C * E + c * E + e],     av[e], sb);
            s1 = fmaf(sw[2 * C * E + c * E + e], av[e], s1);
        }
        pa[c * NN + idx] = sa;
        pb[c * NN + idx] = sb;
        pa1[c * NN + idx] = s1;
    }
}

// ---------------- generic tiled SGEMM with norm fused into operand/epilogue ----------------
// C[m,n] = rowsc[m] * sum_k A_eff[m,k] * B[k,n]  (optionally relu)
// A_eff[m,k] = ((diag_mode && m==k) ? (diag_mode==1 ? 0 : 1) : Araw) * colsc[k]
// TRANSA: underlying A stored [k,m] row-major (computes A^T @ B)
template <int BM, int BN, int BK, int TM, int TN, bool TRANSA>
__global__ __launch_bounds__((BM / TM) * (BN / TN))
void gemm_k(const float* __restrict__ A, const float* __restrict__ B, float* __restrict__ Cp,
            int M, int Nc, int K, int lda, int ldb, int ldc,
            size_t sA, size_t sB, size_t sC,
            const float* __restrict__ colsc, size_t sCol, int diag_mode,
            const float* __restrict__ rowsc, size_t sRow, int do_relu) {
    constexpr int NTHREADS = (BM / TM) * (BN / TN);
    __shared__ float As[BK][BM];
    __shared__ float Bs[BK][BN];
    const int z = blockIdx.z;
    A  += (size_t)z * sA;
    B  += (size_t)z * sB;
    Cp += (size_t)z * sC;
    const float* csc = colsc ? colsc + (size_t)z * sCol : nullptr;
    const float* rsc = rowsc ? rowsc + (size_t)z * sRow : nullptr;

    const int tid = threadIdx.x;
    const int m0 = blockIdx.y * BM, n0 = blockIdx.x * BN;
    constexpr int TX = BN / TN;
    const int tx = tid % TX, ty = tid / TX;

    float acc[TM][TN];
    #pragma unroll
    for (int i = 0; i < TM; i++)
        #pragma unroll
        for (int j = 0; j < TN; j++) acc[i][j] = 0.f;

    for (int k0 = 0; k0 < K; k0 += BK) {
        if (!TRANSA) {
            constexpr int NV = (BM * BK) / (NTHREADS * 4);
            #pragma unroll
            for (int e = 0; e < NV; e++) {
                int idx = tid + e * NTHREADS;            // over BM * (BK/4)
                int mm = idx / (BK / 4), kv = idx % (BK / 4);
                int gm = m0 + mm, gk = k0 + kv * 4;
                float4 v = *(const float4*)(A + (size_t)gm * lda + gk);
                float vv[4] = {v.x, v.y, v.z, v.w};
                #pragma unroll
                for (int q = 0; q < 4; q++) {
                    float x = vv[q];
                    int gkk = gk + q;
                    if (diag_mode && gm == gkk) x = (diag_mode == 1) ? 0.f : 1.f;
                    if (csc) x *= csc[gkk];
                    As[kv * 4 + q][mm] = x;
                }
            }
        } else {
            constexpr int NV = (BM * BK) / (NTHREADS * 4);
            #pragma unroll
            for (int e = 0; e < NV; e++) {
                int idx = tid + e * NTHREADS;            // over BK * (BM/4)
                int kk = idx / (BM / 4), mv = idx % (BM / 4);
                int gk = k0 + kk, gm0 = m0 + mv * 4;
                float4 v = *(const float4*)(A + (size_t)gk * lda + gm0);
                float vv[4] = {v.x, v.y, v.z, v.w};
                #pragma unroll
                for (int q = 0; q < 4; q++) {
                    float x = vv[q];
                    if (diag_mode && (gm0 + q) == gk) x = (diag_mode == 1) ? 0.f : 1.f;
                    As[kk][mv * 4 + q] = x;
                }
            }
        }
        {
            constexpr int NV = (BN * BK) / (NTHREADS * 4);
            #pragma unroll
            for (int e = 0; e < NV; e++) {
                int idx = tid + e * NTHREADS;            // over BK * (BN/4)
                int kk = idx / (BN / 4), nv = idx % (BN / 4);
                float4 v = *(const float4*)(B + (size_t)(k0 + kk) * ldb + (n0 + nv * 4));
                *(float4*)&Bs[kk][nv * 4] = v;
            }
        }
        __syncthreads();
        #pragma unroll
        for (int kk = 0; kk < BK; kk++) {
            float ra[TM], rb[TN];
            #pragma unroll
            for (int i = 0; i < TM; i++) ra[i] = As[kk][ty * TM + i];
            #pragma unroll
            for (int j = 0; j < TN; j++) rb[j] = Bs[kk][tx * TN + j];
            #pragma unroll
            for (int i = 0; i < TM; i++)
                #pragma unroll
                for (int j = 0; j < TN; j++) acc[i][j] = fmaf(ra[i], rb[j], acc[i][j]);
        }
        __syncthreads();
    }

    #pragma unroll
    for (int i = 0; i < TM; i++) {
        int gm = m0 + ty * TM + i;
        float rs = rsc ? rsc[gm] : 1.f;
        #pragma unroll
        for (int j = 0; j < TN; j++) {
            float v = acc[i][j] * rs;
            if (do_relu) v = fmaxf(v, 0.f);
            Cp[(size_t)gm * ldc + (n0 + tx * TN + j)] = v;
        }
    }
}

// ---------------- column-degree inverse: cinv[k] = 1/(add + sum_{i!=k} H[i,k]) ----------------
__global__ void colsum_inv_k(const float* __restrict__ H, float* __restrict__ cinv,
                             size_t sH, size_t sC, float add) {
    H += (size_t)blockIdx.z * sH;
    cinv += (size_t)blockIdx.z * sC;
    int col = blockIdx.x * blockDim.x + threadIdx.x;
    float s0 = 0.f, s1 = 0.f, s2 = 0.f, s3 = 0.f;
    for (int i = 0; i < N; i += 4) {
        s0 += H[(size_t)i * N + col];
        s1 += H[(size_t)(i + 1) * N + col];
        s2 += H[(size_t)(i + 2) * N + col];
        s3 += H[(size_t)(i + 3) * N + col];
    }
    float s = ((s0 + s1) + (s2 + s3)) + add - H[(size_t)col * N + col];
    cinv[col] = (s == 0.f) ? 0.f : (1.f / s);
}

// ---------------- Hsum = H2[0] + H2[1] ----------------
__global__ void hsum_k(const float* __restrict__ H2, float* __restrict__ Hs) {
    size_t i = (size_t)blockIdx.x * blockDim.x + threadIdx.x;
    if (i < NN) Hs[i] = H2[i] + H2[NN + i];
}

// ---------------- y = X_o[target_x] @ lin_w^T + lin_b ----------------
__global__ void y_k(const float* __restrict__ Xo, const float* __restrict__ lw,
                    const float* __restrict__ lb, const int* __restrict__ txp,
                    float* __restrict__ outy) {
    int id = blockIdx.x * blockDim.x + threadIdx.x;
    if (id >= NT * NUM_CLASS) return;
    int t = id / NUM_CLASS, k = id % NUM_CLASS;
    const float* xr = Xo + (size_t)txp[t] * W_OUT;
    const float* wr = lw + (size_t)k * W_OUT;
    float s = 0.f;
    #pragma unroll 4
    for (int d = 0; d < W_OUT; d++) s = fmaf(xr[d], wr[d], s);
    outy[id] = s + lb[k];
}

// ---------------- classification loss partials (deterministic fixed-order reduction) ----------------
__global__ void lossC_k(const float* __restrict__ y, const int* __restrict__ tgt,
                        float* __restrict__ part) {
    __shared__ float red[256];
    int t = blockIdx.x * 256 + threadIdx.x;   // grid = NT/256, always valid
    float yv[NUM_CLASS];
    float m = -1e30f;
    #pragma unroll
    for (int k = 0; k < NUM_CLASS; k++) { yv[k] = y[t * NUM_CLASS + k]; m = fmaxf(m, yv[k]); }
    float se = 0.f;
    #pragma unroll
    for (int k = 0; k < NUM_CLASS; k++) se += expf(yv[k] - m);
    float lse = m + logf(se);
    red[threadIdx.x] = yv[tgt[t]] - lse;      // logp at target
    __syncthreads();
    for (int s = 128; s > 0; s >>= 1) {
        if (threadIdx.x < s) red[threadIdx.x] += red[threadIdx.x + s];
        __syncthreads();
    }
    if (threadIdx.x == 0) part[blockIdx.x] = red[0];
}

// ---------------- reconstruction (BCE) loss partials ----------------
__global__ void lossR_k(const float* __restrict__ Xr, const float* __restrict__ X,
                        float* __restrict__ part) {
    __shared__ float red[256];
    const size_t total = (size_t)N * W_IN;
    size_t tid = (size_t)blockIdx.x * 256 + threadIdx.x;
    size_t stride = (size_t)gridDim.x * 256;
    float acc = 0.f;
    for (size_t i = tid; i < total; i += stride) {
        float x = Xr[i];
        if (x > 1.f || x < 0.f) x = 1.f / (1.f + expf(-x));
        float p = fminf(fmaxf(x, 1e-7f), 1.f - 1e-7f);
        float t = X[i];
        acc += t * logf(p) + (1.f - t) * log1pf(-p);
    }
    red[threadIdx.x] = acc;
    __syncthreads();
    for (int s = 128; s > 0; s >>= 1) {
        if (threadIdx.x < s) red[threadIdx.x] += red[threadIdx.x + s];
        __syncthreads();
    }
    if (threadIdx.x == 0) part[blockIdx.x] = red[0];
}

// ---------------- final scalar assembly ----------------
__global__ void final_k(const float* __restrict__ partR, const float* __restrict__ partC,
                        float* __restrict__ out) {
    __shared__ float red[256];
    red[threadIdx.x] = partR[threadIdx.x] + partR[threadIdx.x + 256];
    __syncthreads();
    for (int s = 128; s > 0; s >>= 1) {
        if (threadIdx.x < s) red[threadIdx.x] += red[threadIdx.x + s];
        __syncthreads();
    }
    if (threadIdx.x == 0) {
        float lossR = -red[0] / (float)((size_t)N * W_IN);
        float sC = partC[0] + partC[1] + partC[2] + partC[3];
        float lossC = -sC / (float)NT;
        out[0] = lossC + lossR;
        out[1 + NT * NUM_CLASS + 3 * C * E] = lossR;   // index 8223
    }
}

// ---------------- launch sequence ----------------
extern "C" void kernel_launch(void* const* d_in, const int* in_sizes, int n_in,
                              void* d_out, int out_size) {
    float* S = nullptr;
    cudaGetSymbolAddress((void**)&S, g_scratch);

    const float* A    = (const float*)d_in[0];
    const float* X    = (const float*)d_in[1];
    const float* W    = (const float*)d_in[2];
    const float* W1   = (const float*)d_in[3];
    const float* W2   = (const float*)d_in[4];
    const float* lw   = (const float*)d_in[5];
    const float* lb   = (const float*)d_in[6];
    const float* w0a  = (const float*)d_in[7];
    const float* w0b  = (const float*)d_in[8];
    const float* w1a  = (const float*)d_in[9];
    const int*   txp  = (const int*)d_in[10];
    const int*   tgt  = (const int*)d_in[11];
    float* out = (float*)d_out;

    // 1. softmax weights (also writes Ws outputs)
    softmax_init_k<<<1, 32>>>(w0a, w0b, w1a, S + OFF_SW, out);

    // 2. a, b, a1 = weighted sums of edge-type adjacency (single pass over A)
    gtconv_k<<<(unsigned)((NN + 255) / 256), 256>>>(A, S + OFF_SW, S + OFF_A, S + OFF_B, S + OFF_A1);

    // 3. H[c] = a[c] @ b[c]   (batched over channels)
    gemm_k<128, 128, 16, 8, 8, false><<<dim3(16, 16, 2), 256>>>(
        S + OFF_A, S + OFF_B, S + OFF_H, N, N, N, N, N, N,
        NN, NN, NN, nullptr, 0, 0, nullptr, 0, 0);

    // 4. cinv1[c] = 1/colsum(H[c] with zero diag)
    colsum_inv_k<<<dim3(8, 1, 2), 256>>>(S + OFF_H, S + OFF_CINV1, NN, N, 0.f);

    // 5. H2[c] = (H[c], diag->0, col-scaled) @ a1[c]   -> stored in OFF_A (reuse)
    gemm_k<128, 128, 16, 8, 8, false><<<dim3(16, 16, 2), 256>>>(
        S + OFF_H, S + OFF_A1, S + OFF_A, N, N, N, N, N, N,
        NN, NN, NN, S + OFF_CINV1, N, 1, nullptr, 0, 0);

    // 6. cinv2[c] = 1/(1 + colsum(H2[c] with zero diag))
    colsum_inv_k<<<dim3(8, 1, 2), 256>>>(S + OFF_A, S + OFF_CINV2, NN, N, 1.f);

    // 7. Hsum = H2[0] + H2[1] -> OFF_B (reuse)
    hsum_k<<<(unsigned)(NN / 256), 256>>>(S + OFF_A, S + OFF_B);

    // 8. cinvs = 1/(1 + colsum(Hsum with zero diag))
    colsum_inv_k<<<dim3(8, 1, 1), 256>>>(S + OFF_B, S + OFF_CINVS, 0, 0, 1.f);

    // 9. XW = X @ W
    gemm_k<64, 64, 16, 4, 4, false><<<dim3(W_OUT / 64, N / 64, 1), 256>>>(
        X, W, S + OFF_XW, N, W_OUT, W_IN, W_IN, W_OUT, W_OUT,
        0, 0, 0, nullptr, 0, 0, nullptr, 0, 0);

    // 10. Xc[c] = relu(cinv2[c] * (H2[c] diag->1)^T @ XW) written into X_cat columns [c*128, ...)
    gemm_k<64, 64, 16, 4, 4, true><<<dim3(W_OUT / 64, N / 64, 2), 256>>>(
        S + OFF_A, S + OFF_XW, S + OFF_XCAT, N, W_OUT, N, N, W_OUT, C * W_OUT,
        NN, 0, (size_t)W_OUT, nullptr, 0, 2, S + OFF_CINV2, N, 1);

    // 11. XCW1 = X_cat @ W1 ; XCW2 = X_cat @ W2
    gemm_k<64, 64, 16, 4, 4, false><<<dim3(W_OUT / 64, N / 64, 1), 256>>>(
        S + OFF_XCAT, W1, S + OFF_XCW1, N, W_OUT, C * W_OUT, C * W_OUT, W_OUT, W_OUT,
        0, 0, 0, nullptr, 0, 0, nullptr, 0, 0);
    gemm_k<64, 64, 16, 4, 4, false><<<dim3(W_IN / 64, N / 64, 1), 256>>>(
        S + OFF_XCAT, W2, S + OFF_XCW2, N, W_IN, C * W_OUT, C * W_OUT, W_IN, W_IN,
        0, 0, 0, nullptr, 0, 0, nullptr, 0, 0);

    // 12. X_o = cinvs * (Hsum diag->1)^T @ XCW1 ; X_r = cinvs * (Hsum diag->1)^T @ XCW2
    gemm_k<64, 64, 16, 4, 4, true><<<dim3(W_OUT / 64, N / 64, 1), 256>>>(
        S + OFF_B, S + OFF_XCW1, S + OFF_XO, N, W_OUT, N, N, W_OUT, W_OUT,
        0, 0, 0, nullptr, 0, 2, S + OFF_CINVS, 0, 0);
    gemm_k<64, 64, 16, 4, 4, true><<<dim3(W_IN / 64, N / 64, 1), 256>>>(
        S + OFF_B, S + OFF_XCW2, S + OFF_XR, N, W_IN, N, N, W_IN, W_IN,
        0, 0, 0, nullptr, 0, 2, S + OFF_CINVS, 0, 0);

    // 13. y (written straight into d_out[1..8192])
    y_k<<<(NT * NUM_CLASS) / 256, 256>>>(S + OFF_XO, lw, lb, txp, out + 1);

    // 14. losses (deterministic partials)
    lossC_k<<<NT / 256, 256>>>(out + 1, tgt, S + OFF_PARTC);
    lossR_k<<<512, 256>>>(S + OFF_XR, X, S + OFF_PARTR);

    // 15. final scalars
    final_k<<<1, 256>>>(S + OFF_PARTR, S + OFF_PARTC, out);
}

// round 2
// speedup vs baseline: 1.0025x; 1.0025x over previous
#include <cuda_runtime.h>
#include <math.h>

// ---------------- problem constants ----------------
constexpr int N = 2048, E = 5, C = 2, W_IN = 256, W_OUT = 128, NUM_CLASS = 8, NT = 1024;
constexpr size_t NN = (size_t)N * (size_t)N;

// ---------------- scratch layout (floats) ----------------
constexpr size_t OFF_A     = 0;                                   // a [C,N,N]; later H2 [C,N,N]
constexpr size_t OFF_B     = OFF_A  + C * NN;                     // b [C,N,N]; later Hsum [N,N]
constexpr size_t OFF_A1    = OFF_B  + C * NN;                     // a1 [C,N,N]
constexpr size_t OFF_H     = OFF_A1 + C * NN;                     // H [C,N,N]
constexpr size_t OFF_CINV1 = OFF_H  + C * NN;                     // [C,N]
constexpr size_t OFF_CINV2 = OFF_CINV1 + (size_t)C * N;           // [C,N]
constexpr size_t OFF_CINVS = OFF_CINV2 + (size_t)C * N;           // [N]
constexpr size_t OFF_XW    = OFF_CINVS + N;                       // [N,128]
constexpr size_t OFF_XCAT  = OFF_XW   + (size_t)N * W_OUT;        // [N,256]
constexpr size_t OFF_XCW1  = OFF_XCAT + (size_t)N * (C * W_OUT);  // [N,128]
constexpr size_t OFF_XCW2  = OFF_XCW1 + (size_t)N * W_OUT;        // [N,256]
constexpr size_t OFF_XO    = OFF_XCW2 + (size_t)N * W_IN;         // [N,128]
constexpr size_t OFF_XR    = OFF_XO   + (size_t)N * W_OUT;        // [N,256]
constexpr size_t OFF_SW    = OFF_XR   + (size_t)N * W_IN;         // 30 softmax weights (pad 32)
constexpr size_t OFF_PARTR = OFF_SW + 32;                         // 512 partials
constexpr size_t OFF_PARTC = OFF_PARTR + 512;                     // 4 partials (pad 16)
constexpr size_t SCRATCH_FLOATS = OFF_PARTC + 16;

__device__ __align__(256) float g_scratch[SCRATCH_FLOATS];

// ---------------- softmax of the three [C,E] weights + write Ws outputs ----------------
__global__ void softmax_init_k(const float* __restrict__ w0a, const float* __restrict__ w0b,
                               const float* __restrict__ w1a, float* __restrict__ sw,
                               float* __restrict__ out) {
    int r = threadIdx.x;
    if (r < 3 * C) {
        int t = r >> 1, c = r & 1;
        const float* src = (t == 0) ? w0a : (t == 1) ? w0b : w1a;
        src += c * E;
        float v[E]; float m = -1e30f;
        #pragma unroll
        for (int e = 0; e < E; e++) { v[e] = src[e]; m = fmaxf(m, v[e]); }
        float s = 0.f;
        #pragma unroll
        for (int e = 0; e < E; e++) { v[e] = expf(v[e] - m); s += v[e]; }
        #pragma unroll
        for (int e = 0; e < E; e++) {
            float q = v[e] / s;
            sw[t * (C * E) + c * E + e] = q;
            out[1 + NT * NUM_CLASS + t * (C * E) + c * E + e] = q;
        }
    }
}

// ---------------- fused GT conv: a,b,a1 = einsum(softmax(w), A) in one pass over A ----------------
__global__ void gtconv_k(const float* __restrict__ A, const float* __restrict__ sw,
                         float* __restrict__ pa, float* __restrict__ pb, float* __restrict__ pa1) {
    size_t idx = (size_t)blockIdx.x * blockDim.x + threadIdx.x;
    if (idx >= NN) return;
    float av[E];
    #pragma unroll
    for (int e = 0; e < E; e++) av[e] = A[idx * E + e];
    #pragma unroll
    for (int c = 0; c < C; c++) {
        float sa = 0.f, sb = 0.f, s1 = 0.f;
        #pragma unroll
        for (int e = 0; e < E; e++) {
            sa = fmaf(sw[c * E + e],             av[e], sa);
            sb = fmaf(sw[C * E + c * E + e],     av[e], sb);
            s1 = fmaf(sw[2 * C * E + c * E + e], av[e], s1);
        }
        pa[c * NN + idx] = sa;
        pb[c * NN + idx] = sb;
        pa1[c * NN + idx] = s1;
    }
}

// ---------------- generic tiled SGEMM with norm fused into operand/epilogue ----------------
// C[m,n] = rowsc[m] * sum_k A_eff[m,k] * B[k,n]  (optionally relu)
// A_eff[m,k] = ((diag_mode && m==k) ? (diag_mode==1 ? 0 : 1) : Araw) * colsc[k]
// TRANSA: underlying A stored [k,m] row-major (computes A^T @ B)
template <int BM, int BN, int BK, int TM, int TN, bool TRANSA>
__global__ __launch_bounds__((BM / TM) * (BN / TN))
void gemm_k(const float* __restrict__ A, const float* __restrict__ B, float* __restrict__ Cp,
            int M, int Nc, int K, int lda, int ldb, int ldc,
            size_t sA, size_t sB, size_t sC,
            const float* __restrict__ colsc, size_t sCol, int diag_mode,
            const float* __restrict__ rowsc, size_t sRow, int do_relu) {
    constexpr int NTHREADS = (BM / TM) * (BN / TN);
    __shared__ float As[BK][BM];
    __shared__ float Bs[BK][BN];
    const int z = blockIdx.z;
    A  += (size_t)z * sA;
    B  += (size_t)z * sB;
    Cp += (size_t)z * sC;
    const float* csc = colsc ? colsc + (size_t)z * sCol : nullptr;
    const float* rsc = rowsc ? rowsc + (size_t)z * sRow : nullptr;

    const int tid = threadIdx.x;
    const int m0 = blockIdx.y * BM, n0 = blockIdx.x * BN;
    constexpr int TX = BN / TN;
    const int tx = tid % TX, ty = tid / TX;

    float acc[TM][TN];
    #pragma unroll
    for (int i = 0; i < TM; i++)
        #pragma unroll
        for (int j = 0; j < TN; j++) acc[i][j] = 0.f;

    for (int k0 = 0; k0 < K; k0 += BK) {
        if (!TRANSA) {
            constexpr int NV = (BM * BK) / (NTHREADS * 4);
            #pragma unroll
            for (int e = 0; e < NV; e++) {
                int idx = tid + e * NTHREADS;            // over BM * (BK/4)
                int mm = idx / (BK / 4), kv = idx % (BK / 4);
                int gm = m0 + mm, gk = k0 + kv * 4;
                float4 v = *(const float4*)(A + (size_t)gm * lda + gk);
                float vv[4] = {v.x, v.y, v.z, v.w};
                #pragma unroll
                for (int q = 0; q < 4; q++) {
                    float x = vv[q];
                    int gkk = gk + q;
                    if (diag_mode && gm == gkk) x = (diag_mode == 1) ? 0.f : 1.f;
                    if (csc) x *= csc[gkk];
                    As[kv * 4 + q][mm] = x;
                }
            }
        } else {
            constexpr int NV = (BM * BK) / (NTHREADS * 4);
            #pragma unroll
            for (int e = 0; e < NV; e++) {
                int idx = tid + e * NTHREADS;            // over BK * (BM/4)
                int kk = idx / (BM / 4), mv = idx % (BM / 4);
                int gk = k0 + kk, gm0 = m0 + mv * 4;
                float4 v = *(const float4*)(A + (size_t)gk * lda + gm0);
                float vv[4] = {v.x, v.y, v.z, v.w};
                #pragma unroll
                for (int q = 0; q < 4; q++) {
                    float x = vv[q];
                    if (diag_mode && (gm0 + q) == gk) x = (diag_mode == 1) ? 0.f : 1.f;
                    As[kk][mv * 4 + q] = x;
                }
            }
        }
        {
            constexpr int NV = (BN * BK) / (NTHREADS * 4);
            #pragma unroll
            for (int e = 0; e < NV; e++) {
                int idx = tid + e * NTHREADS;            // over BK * (BN/4)
                int kk = idx / (BN / 4), nv = idx % (BN / 4);
                float4 v = *(const float4*)(B + (size_t)(k0 + kk) * ldb + (n0 + nv * 4));
                *(float4*)&Bs[kk][nv * 4] = v;
            }
        }
        __syncthreads();
        #pragma unroll
        for (int kk = 0; kk < BK; kk++) {
            float ra[TM], rb[TN];
            #pragma unroll
            for (int i = 0; i < TM; i++) ra[i] = As[kk][ty * TM + i];
            #pragma unroll
            for (int j = 0; j < TN; j++) rb[j] = Bs[kk][tx * TN + j];
            #pragma unroll
            for (int i = 0; i < TM; i++)
                #pragma unroll
                for (int j = 0; j < TN; j++) acc[i][j] = fmaf(ra[i], rb[j], acc[i][j]);
        }
        __syncthreads();
    }

    #pragma unroll
    for (int i = 0; i < TM; i++) {
        int gm = m0 + ty * TM + i;
        float rs = rsc ? rsc[gm] : 1.f;
        #pragma unroll
        for (int j = 0; j < TN; j++) {
            float v = acc[i][j] * rs;
            if (do_relu) v = fmaxf(v, 0.f);
            Cp[(size_t)gm * ldc + (n0 + tx * TN + j)] = v;
        }
    }
}

// ---------------- column-degree inverse: cinv[k] = 1/(add + sum_{i!=k} H[i,k]) ----------------
__global__ void colsum_inv_k(const float* __restrict__ H, float* __restrict__ cinv,
                             size_t sH, size_t sC, float add) {
    H += (size_t)blockIdx.z * sH;
    cinv += (size_t)blockIdx.z * sC;
    int col = blockIdx.x * blockDim.x + threadIdx.x;
    float s0 = 0.f, s1 = 0.f, s2 = 0.f, s3 = 0.f;
    for (int i = 0; i < N; i += 4) {
        s0 += H[(size_t)i * N + col];
        s1 += H[(size_t)(i + 1) * N + col];
        s2 += H[(size_t)(i + 2) * N + col];
        s3 += H[(size_t)(i + 3) * N + col];
    }
    float s = ((s0 + s1) + (s2 + s3)) + add - H[(size_t)col * N + col];
    cinv[col] = (s == 0.f) ? 0.f : (1.f / s);
}

// ---------------- Hsum = H2[0] + H2[1] ----------------
__global__ void hsum_k(const float* __restrict__ H2, float* __restrict__ Hs) {
    size_t i = (size_t)blockIdx.x * blockDim.x + threadIdx.x;
    if (i < NN) Hs[i] = H2[i] + H2[NN + i];
}

// ---------------- y = X_o[target_x] @ lin_w^T + lin_b ----------------
__global__ void y_k(const float* __restrict__ Xo, const float* __restrict__ lw,
                    const float* __restrict__ lb, const int* __restrict__ txp,
                    float* __restrict__ outy) {
    int id = blockIdx.x * blockDim.x + threadIdx.x;
    if (id >= NT * NUM_CLASS) return;
    int t = id / NUM_CLASS, k = id % NUM_CLASS;
    const float* xr = Xo + (size_t)txp[t] * W_OUT;
    const float* wr = lw + (size_t)k * W_OUT;
    float s = 0.f;
    #pragma unroll 4
    for (int d = 0; d < W_OUT; d++) s = fmaf(xr[d], wr[d], s);
    outy[id] = s + lb[k];
}

// ---------------- classification loss partials (deterministic fixed-order reduction) ----------------
__global__ void lossC_k(const float* __restrict__ y, const int* __restrict__ tgt,
                        float* __restrict__ part) {
    __shared__ float red[256];
    int t = blockIdx.x * 256 + threadIdx.x;   // grid = NT/256, always valid
    float yv[NUM_CLASS];
    float m = -1e30f;
    #pragma unroll
    for (int k = 0; k < NUM_CLASS; k++) { yv[k] = y[t * NUM_CLASS + k]; m = fmaxf(m, yv[k]); }
    float se = 0.f;
    #pragma unroll
    for (int k = 0; k < NUM_CLASS; k++) se += expf(yv[k] - m);
    float lse = m + logf(se);
    red[threadIdx.x] = yv[tgt[t]] - lse;      // logp at target
    __syncthreads();
    for (int s = 128; s > 0; s >>= 1) {
        if (threadIdx.x < s) red[threadIdx.x] += red[threadIdx.x + s];
        __syncthreads();
    }
    if (threadIdx.x == 0) part[blockIdx.x] = red[0];
}

// ---------------- reconstruction (BCE) loss partials ----------------
__global__ void lossR_k(const float* __restrict__ Xr, const float* __restrict__ X,
                        float* __restrict__ part) {
    __shared__ float red[256];
    const size_t total = (size_t)N * W_IN;
    size_t tid = (size_t)blockIdx.x * 256 + threadIdx.x;
    size_t stride = (size_t)gridDim.x * 256;
    float acc = 0.f;
    for (size_t i = tid; i < total; i += stride) {
        float x = Xr[i];
        if (x > 1.f || x < 0.f) x = 1.f / (1.f + expf(-x));
        float p = fminf(fmaxf(x, 1e-7f), 1.f - 1e-7f);
        float t = X[i];
        acc += t * logf(p) + (1.f - t) * log1pf(-p);
    }
    red[threadIdx.x] = acc;
    __syncthreads();
    for (int s = 128; s > 0; s >>= 1) {
        if (threadIdx.x < s) red[threadIdx.x] += red[threadIdx.x + s];
        __syncthreads();
    }
    if (threadIdx.x == 0) part[blockIdx.x] = red[0];
}

// ---------------- final scalar assembly ----------------
__global__ void final_k(const float* __restrict__ partR, const float* __restrict__ partC,
                        float* __restrict__ out) {
    __shared__ float red[256];
    red[threadIdx.x] = partR[threadIdx.x] + partR[threadIdx.x + 256];
    __syncthreads();
    for (int s = 128; s > 0; s >>= 1) {
        if (threadIdx.x < s) red[threadIdx.x] += red[threadIdx.x + s];
        __syncthreads();
    }
    if (threadIdx.x == 0) {
        float lossR = -red[0] / (float)((size_t)N * W_IN);
        float sC = partC[0] + partC[1] + partC[2] + partC[3];
        float lossC = -sC / (float)NT;
        out[0] = lossC + lossR;
        out[1 + NT * NUM_CLASS + 3 * C * E] = lossR;   // index 8223
    }
}

// ---------------- launch sequence ----------------
extern "C" void kernel_launch(void* const* d_in, const int* in_sizes, int n_in,
                              void* d_out, int out_size) {
    float* S = nullptr;
    cudaGetSymbolAddress((void**)&S, g_scratch);

    const float* A    = (const float*)d_in[0];
    const float* X    = (const float*)d_in[1];
    const float* W    = (const float*)d_in[2];
    const float* W1   = (const float*)d_in[3];
    const float* W2   = (const float*)d_in[4];
    const float* lw   = (const float*)d_in[5];
    const float* lb   = (const float*)d_in[6];
    const float* w0a  = (const float*)d_in[7];
    const float* w0b  = (const float*)d_in[8];
    const float* w1a  = (const float*)d_in[9];
    const int*   txp  = (const int*)d_in[10];
    const int*   tgt  = (const int*)d_in[11];
    float* out = (float*)d_out;

    // 1. softmax weights (also writes Ws outputs)
    softmax_init_k<<<1, 32>>>(w0a, w0b, w1a, S + OFF_SW, out);

    // 2. a, b, a1 = weighted sums of edge-type adjacency (single pass over A)
    gtconv_k<<<(unsigned)((NN + 255) / 256), 256>>>(A, S + OFF_SW, S + OFF_A, S + OFF_B, S + OFF_A1);

    // 3. H[c] = a[c] @ b[c]   (batched over channels)
    gemm_k<128, 128, 16, 8, 8, false><<<dim3(16, 16, 2), 256>>>(
        S + OFF_A, S + OFF_B, S + OFF_H, N, N, N, N, N, N,
        NN, NN, NN, nullptr, 0, 0, nullptr, 0, 0);

    // 4. cinv1[c] = 1/colsum(H[c] with zero diag)
    colsum_inv_k<<<dim3(8, 1, 2), 256>>>(S + OFF_H, S + OFF_CINV1, NN, N, 0.f);

    // 5. H2[c] = (H[c], diag->0, col-scaled) @ a1[c]   -> stored in OFF_A (reuse)
    gemm_k<128, 128, 16, 8, 8, false><<<dim3(16, 16, 2), 256>>>(
        S + OFF_H, S + OFF_A1, S + OFF_A, N, N, N, N, N, N,
        NN, NN, NN, S + OFF_CINV1, N, 1, nullptr, 0, 0);

    // 6. cinv2[c] = 1/(1 + colsum(H2[c] with zero diag))
    colsum_inv_k<<<dim3(8, 1, 2), 256>>>(S + OFF_A, S + OFF_CINV2, NN, N, 1.f);

    // 7. Hsum = H2[0] + H2[1] -> OFF_B (reuse)
    hsum_k<<<(unsigned)(NN / 256), 256>>>(S + OFF_A, S + OFF_B);

    // 8. cinvs = 1/(1 + colsum(Hsum with zero diag))
    colsum_inv_k<<<dim3(8, 1, 1), 256>>>(S + OFF_B, S + OFF_CINVS, 0, 0, 1.f);

    // 9. XW = X @ W
    gemm_k<64, 64, 16, 4, 4, false><<<dim3(W_OUT / 64, N / 64, 1), 256>>>(
        X, W, S + OFF_XW, N, W_OUT, W_IN, W_IN, W_OUT, W_OUT,
        0, 0, 0, nullptr, 0, 0, nullptr, 0, 0);

    // 10. Xc[c] = relu(cinv2[c] * (H2[c] diag->1)^T @ XW) written into X_cat columns [c*128, ...)
    gemm_k<64, 64, 16, 4, 4, true><<<dim3(W_OUT / 64, N / 64, 2), 256>>>(
        S + OFF_A, S + OFF_XW, S + OFF_XCAT, N, W_OUT, N, N, W_OUT, C * W_OUT,
        NN, 0, (size_t)W_OUT, nullptr, 0, 2, S + OFF_CINV2, N, 1);

    // 11. XCW1 = X_cat @ W1 ; XCW2 = X_cat @ W2
    gemm_k<64, 64, 16, 4, 4, false><<<dim3(W_OUT / 64, N / 64, 1), 256>>>(
        S + OFF_XCAT, W1, S + OFF_XCW1, N, W_OUT, C * W_OUT, C * W_OUT, W_OUT, W_OUT,
        0, 0, 0, nullptr, 0, 0, nullptr, 0, 0);
    gemm_k<64, 64, 16, 4, 4, false><<<dim3(W_IN / 64, N / 64, 1), 256>>>(
        S + OFF_XCAT, W2, S + OFF_XCW2, N, W_IN, C * W_OUT, C * W_OUT, W_IN, W_IN,
        0, 0, 0, nullptr, 0, 0, nullptr, 0, 0);

    // 12. X_o = cinvs * (Hsum diag->1)^T @ XCW1 ; X_r = cinvs * (Hsum diag->1)^T @ XCW2
    gemm_k<64, 64, 16, 4, 4, true><<<dim3(W_OUT / 64, N / 64, 1), 256>>>(
        S + OFF_B, S + OFF_XCW1, S + OFF_XO, N, W_OUT, N, N, W_OUT, W_OUT,
        0, 0, 0, nullptr, 0, 2, S + OFF_CINVS, 0, 0);
    gemm_k<64, 64, 16, 4, 4, true><<<dim3(W_IN / 64, N / 64, 1), 256>>>(
        S + OFF_B, S + OFF_XCW2, S + OFF_XR, N, W_IN, N, N, W_IN, W_IN,
        0, 0, 0, nullptr, 0, 2, S + OFF_CINVS, 0, 0);

    // 13. y (written straight into d_out[1..8192])
    y_k<<<(NT * NUM_CLASS) / 256, 256>>>(S + OFF_XO, lw, lb, txp, out + 1);

    // 14. losses (deterministic partials)
    lossC_k<<<NT / 256, 256>>>(out + 1, tgt, S + OFF_PARTC);
    lossR_k<<<512, 256>>>(S + OFF_XR, X, S + OFF_PARTR);

    // 15. final scalars
    final_k<<<1, 256>>>(S + OFF_PARTR, S + OFF_PARTC, out);
}

// round 8
// speedup vs baseline: 3.1208x; 3.1131x over previous
#include <cuda_runtime.h>
#include <math.h>
#include <stdint.h>

constexpr int N = 2048, E = 5, C = 2, W_IN = 256, W_OUT = 128, NUM_CLASS = 8, NT = 1024;
constexpr size_t NN = (size_t)N * (size_t)N;

// ---------------- scratch layout (floats) ----------------
constexpr size_t OFF_A    = 0;                              // a [C,N,N] tf32
constexpr size_t OFF_B    = 2 * NN;                         // b [C,N,N] tf32
constexpr size_t OFF_A1   = 4 * NN;                         // a1; later cinv1-row-scaled, tf32
constexpr size_t OFF_H    = 6 * NN;                         // H diag->0, tf32
constexpr size_t OFF_H2   = 8 * NN;                         // H2 diag->1, tf32
constexpr size_t OFF_HS   = 10 * NN;                        // Hs = H2[0]+H2[1], diag->1, tf32
constexpr size_t OFF_XW   = 11 * NN;                        // [N,128] tf32
constexpr size_t OFF_XCAT = OFF_XW   + (size_t)N * 128;     // [N,256]
constexpr size_t OFF_XCW  = OFF_XCAT + (size_t)N * 256;     // [N,384] tf32 (W1 cols|W2 cols)
constexpr size_t OFF_XOR  = OFF_XCW  + (size_t)N * 384;     // [N,384] (Xo|Xr)
constexpr size_t OFF_CI1  = OFF_XOR  + (size_t)N * 384;     // [C,N]
constexpr size_t OFF_CI2  = OFF_CI1  + (size_t)C * N;       // [C,N]
constexpr size_t OFF_CIS  = OFF_CI2  + (size_t)C * N;       // [N]
constexpr size_t OFF_COLP = OFF_CIS  + N;                   // [2,16,N]
constexpr size_t OFF_SW   = OFF_COLP + (size_t)2 * 16 * N;  // 30 (pad 32)
constexpr size_t OFF_PR   = OFF_SW + 32;                    // 512
constexpr size_t OFF_PC   = OFF_PR + 512;                   // 16
constexpr size_t SCRATCH_FLOATS = OFF_PC + 16;

__device__ __align__(1024) float g_scratch[SCRATCH_FLOATS];

// ============================ helpers ============================
__device__ __forceinline__ uint32_t smem_u32(const void* p) {
    uint32_t a;
    asm("{ .reg .u64 t; cvta.to.shared.u64 t, %1; cvt.u32.u64 %0, t; }" : "=r"(a) : "l"(p));
    return a;
}
__device__ __forceinline__ float tf32r(float x) {
    uint32_t u;
    asm("cvt.rna.tf32.f32 %0, %1;" : "=r"(u) : "f"(x));
    return __uint_as_float(u);
}
__device__ __forceinline__ void cpa16(uint32_t saddr, const void* g) {
    asm volatile("cp.async.cg.shared.global [%0], [%1], 16;" :: "r"(saddr), "l"(g));
}
#define CP_COMMIT() asm volatile("cp.async.commit_group;" ::: "memory")
#define CP_WAIT1()  asm volatile("cp.async.wait_group 1;" ::: "memory")
#define CP_WAIT0()  asm volatile("cp.async.wait_group 0;" ::: "memory")

__device__ __forceinline__ void mma1688(float* d, const uint32_t* a, const uint32_t* b) {
    asm volatile(
        "mma.sync.aligned.m16n8k8.row.col.f32.tf32.tf32.f32 "
        "{%0,%1,%2,%3}, {%4,%5,%6,%7}, {%8,%9}, {%0,%1,%2,%3};"
        : "+f"(d[0]), "+f"(d[1]), "+f"(d[2]), "+f"(d[3])
        : "r"(a[0]), "r"(a[1]), "r"(a[2]), "r"(a[3]), "r"(b[0]), "r"(b[1]));
}

// ============================ tensor GEMM ============================
// C[m, coff+n] = rowsc[m] * sum_k Aop[m,k] * B[k,n]
//   TRANSA=false: Aop = A[m][k] (row-major). TRANSA=true: Aop = A[k][m] (A^T).
// flags: 1=relu, 2=diag->0, 4=diag->1, 8=tf32-round output
// BM=BN=128, BK=32; 256 threads; 8 warps (2m x 4n), warp tile 64x32.
template <bool TRANSA>
__global__ void __launch_bounds__(256)
tgemm_k(const float* __restrict__ A, const float* __restrict__ B, float* __restrict__ Cc,
        int K, int lda, int ldb, int ldc,
        size_t szA, size_t szB, size_t szC, int n_off,
        const float* __restrict__ rowsc, size_t sRow, int flags) {
    extern __shared__ float smem[];
    constexpr int A_FLOATS = TRANSA ? 32 * 136 : 128 * 36;
    constexpr int B_FLOATS = 32 * 136;
    constexpr int STAGE = A_FLOATS + B_FLOATS;

    const int tid = threadIdx.x, lane = tid & 31, wid = tid >> 5;
    const int wm = wid >> 2, wn = wid & 3;
    const int m0 = blockIdx.y * 128, n0 = blockIdx.x * 128;
    const int z = blockIdx.z;
    A += (size_t)z * szA;
    B += (size_t)z * szB;
    Cc += (size_t)z * szC;
    const int coff = z * n_off;
    const uint32_t sb = smem_u32(smem);

    float acc[4][4][4] = {};

    auto fill = [&](int s, int k0) {
        uint32_t sa = sb + s * STAGE * 4;
        uint32_t sbb = sa + A_FLOATS * 4;
        #pragma unroll
        for (int e = 0; e < 4; e++) {
            int chunk = tid + e * 256;
            if (!TRANSA) {
                int m = chunk >> 3, kv = chunk & 7;
                cpa16(sa + (m * 36 + kv * 4) * 4, A + (size_t)(m0 + m) * lda + k0 + kv * 4);
            } else {
                int kk = chunk >> 5, mv = chunk & 31;
                cpa16(sa + (kk * 136 + mv * 4) * 4, A + (size_t)(k0 + kk) * lda + m0 + mv * 4);
            }
        }
        #pragma unroll
        for (int e = 0; e < 4; e++) {
            int chunk = tid + e * 256;
            int kk = chunk >> 5, nv = chunk & 31;
            cpa16(sbb + (kk * 136 + nv * 4) * 4, B + (size_t)(k0 + kk) * ldb + n0 + nv * 4);
        }
        CP_COMMIT();
    };

    const int niter = K / 32;
    fill(0, 0);
    for (int kt = 0; kt < niter; kt++) {
        if (kt + 1 < niter) { fill((kt + 1) & 1, (kt + 1) * 32); CP_WAIT1(); }
        else CP_WAIT0();
        __syncthreads();
        const float* As = smem + (kt & 1) * STAGE;
        const float* Bs = As + A_FLOATS;
        #pragma unroll
        for (int ks = 0; ks < 4; ks++) {
            uint32_t af[4][4], bf[4][2];
            const int ak = ks * 8 + (lane & 3);
            const int ar = lane >> 2;
            #pragma unroll
            for (int mt = 0; mt < 4; mt++) {
                int r = wm * 64 + mt * 16 + ar;
                if (!TRANSA) {
                    af[mt][0] = __float_as_uint(As[r * 36 + ak]);
                    af[mt][1] = __float_as_uint(As[(r + 8) * 36 + ak]);
                    af[mt][2] = __float_as_uint(As[r * 36 + ak + 4]);
                    af[mt][3] = __float_as_uint(As[(r + 8) * 36 + ak + 4]);
                } else {
                    af[mt][0] = __float_as_uint(As[ak * 136 + r]);
                    af[mt][1] = __float_as_uint(As[ak * 136 + r + 8]);
                    af[mt][2] = __float_as_uint(As[(ak + 4) * 136 + r]);
                    af[mt][3] = __float_as_uint(As[(ak + 4) * 136 + r + 8]);
                }
            }
            #pragma unroll
            for (int nt = 0; nt < 4; nt++) {
                int ccl = wn * 32 + nt * 8 + ar;
                bf[nt][0] = __float_as_uint(Bs[ak * 136 + ccl]);
                bf[nt][1] = __float_as_uint(Bs[(ak + 4) * 136 + ccl]);
            }
            #pragma unroll
            for (int mt = 0; mt < 4; mt++)
                #pragma unroll
                for (int nt = 0; nt < 4; nt++)
                    mma1688(acc[mt][nt], af[mt], bf[nt]);
        }
        __syncthreads();
    }

    #pragma unroll
    for (int mt = 0; mt < 4; mt++) {
        int rbase = m0 + wm * 64 + mt * 16 + (lane >> 2);
        #pragma unroll
        for (int half = 0; half < 2; half++) {
            int r = rbase + half * 8;
            float rs = rowsc ? rowsc[(size_t)z * sRow + r] : 1.f;
            #pragma unroll
            for (int nt = 0; nt < 4; nt++) {
                int cc = n0 + wn * 32 + nt * 8 + (lane & 3) * 2;
                float v0 = acc[mt][nt][half * 2 + 0] * rs;
                float v1 = acc[mt][nt][half * 2 + 1] * rs;
                if (flags & 1) { v0 = fmaxf(v0, 0.f); v1 = fmaxf(v1, 0.f); }
                if (flags & 2) { if (r == cc) v0 = 0.f; if (r == cc + 1) v1 = 0.f; }
                if (flags & 4) { if (r == cc) v0 = 1.f; if (r == cc + 1) v1 = 1.f; }
                if (flags & 8) { v0 = tf32r(v0); v1 = tf32r(v1); }
                *(float2*)(Cc + (size_t)r * ldc + coff + cc) = make_float2(v0, v1);
            }
        }
    }
}

// ============================ small kernels ============================
__global__ void softmax_init_k(const float* __restrict__ w0a, const float* __restrict__ w0b,
                               const float* __restrict__ w1a, float* __restrict__ sw,
                               float* __restrict__ out) {
    int r = threadIdx.x;
    if (r < 3 * C) {
        int t = r >> 1, c = r & 1;
        const float* src = (t == 0) ? w0a : (t == 1) ? w0b : w1a;
        src += c * E;
        float v[E]; float m = -1e30f;
        #pragma unroll
        for (int e = 0; e < E; e++) { v[e] = src[e]; m = fmaxf(m, v[e]); }
        float s = 0.f;
        #pragma unroll
        for (int e = 0; e < E; e++) { v[e] = expf(v[e] - m); s += v[e]; }
        #pragma unroll
        for (int e = 0; e < E; e++) {
            float q = v[e] / s;
            sw[t * (C * E) + c * E + e] = q;
            out[1 + NT * NUM_CLASS + t * (C * E) + c * E + e] = q;
        }
    }
}

__global__ void gtconv_k(const float* __restrict__ A, const float* __restrict__ sw,
                         float* __restrict__ pa, float* __restrict__ pb, float* __restrict__ pa1) {
    size_t idx = (size_t)blockIdx.x * blockDim.x + threadIdx.x;
    if (idx >= NN) return;
    float av[E];
    #pragma unroll
    for (int e = 0; e < E; e++) av[e] = A[idx * E + e];
    #pragma unroll
    for (int c = 0; c < C; c++) {
        float sa = 0.f, sb = 0.f, s1 = 0.f;
        #pragma unroll
        for (int e = 0; e < E; e++) {
            sa = fmaf(sw[c * E + e], av[e], sa);
            sb = fmaf(sw[C * E + c * E + e], av[e], sb);
            s1 = fmaf(sw[2 * C * E + c * E + e], av[e], s1);
        }
        pa[c * NN + idx] = tf32r(sa);
        pb[c * NN + idx] = tf32r(sb);
        pa1[c * NN + idx] = s1;   // rounded later after cinv1 scaling
    }
}

// a1[z][k][j] = tf32r(a1[z][k][j] * cinv1[z][k])   (in place)
__global__ void scale_a1_k(float* __restrict__ a1, const float* __restrict__ cinv1) {
    int col = blockIdx.x * 256 + threadIdx.x;
    int row = blockIdx.y;
    int z = blockIdx.z;
    size_t i = (size_t)z * NN + (size_t)row * N + col;
    a1[i] = tf32r(a1[i] * cinv1[z * N + row]);
}

// Hs = tf32r(H2[0]+H2[1]), diag -> 1
__global__ void hsum_k(const float* __restrict__ H2, float* __restrict__ Hs) {
    int col = blockIdx.x * 256 + threadIdx.x;
    int row = blockIdx.y;
    size_t i = (size_t)row * N + col;
    float v = tf32r(H2[i] + H2[NN + i]);
    Hs[i] = (row == col) ? 1.f : v;
}

__global__ void colsum_part_k(const float* __restrict__ H, float* __restrict__ part, size_t sH) {
    int col = blockIdx.x * 256 + threadIdx.x;
    const float* p = H + (size_t)blockIdx.z * sH + (size_t)blockIdx.y * 128 * N + col;
    float s = 0.f;
    #pragma unroll 8
    for (int i = 0; i < 128; i++) s += p[(size_t)i * N];
    part[((size_t)blockIdx.z * 16 + blockIdx.y) * N + col] = s;
}

__global__ void cinv_fin_k(const float* __restrict__ part, float* __restrict__ cinv) {
    int col = blockIdx.x * 256 + threadIdx.x;
    int z = blockIdx.z;
    float s = 0.f;
    #pragma unroll
    for (int r = 0; r < 16; r++) s += part[((size_t)z * 16 + r) * N + col];
    cinv[z * N + col] = (s == 0.f) ? 0.f : 1.f / s;
}

// SIMT GEMM for K<=256 products; rnd => tf32-round at store
template <int BM, int BN, int BK, int TM, int TN>
__global__ __launch_bounds__((BM / TM) * (BN / TN))
void sgemm_k(const float* __restrict__ A, const float* __restrict__ B, float* __restrict__ Cp,
             int K, int lda, int ldb, int ldc, int rnd) {
    constexpr int NTHREADS = (BM / TM) * (BN / TN);
    __shared__ float As[BK][BM];
    __shared__ float Bs[BK][BN];
    const int tid = threadIdx.x;
    const int m0 = blockIdx.y * BM, n0 = blockIdx.x * BN;
    constexpr int TX = BN / TN;
    const int tx = tid % TX, ty = tid / TX;
    float acc[TM][TN];
    #pragma unroll
    for (int i = 0; i < TM; i++)
        #pragma unroll
        for (int j = 0; j < TN; j++) acc[i][j] = 0.f;
    for (int k0 = 0; k0 < K; k0 += BK) {
        constexpr int NV = (BM * BK) / (NTHREADS * 4);
        #pragma unroll
        for (int e = 0; e < NV; e++) {
            int idx = tid + e * NTHREADS;
            int mm = idx / (BK / 4), kv = idx % (BK / 4);
            float4 v = *(const float4*)(A + (size_t)(m0 + mm) * lda + k0 + kv * 4);
            As[kv * 4 + 0][mm] = v.x; As[kv * 4 + 1][mm] = v.y;
            As[kv * 4 + 2][mm] = v.z; As[kv * 4 + 3][mm] = v.w;
        }
        constexpr int NV2 = (BN * BK) / (NTHREADS * 4);
        #pragma unroll
        for (int e = 0; e < NV2; e++) {
            int idx = tid + e * NTHREADS;
            int kk = idx / (BN / 4), nv = idx % (BN / 4);
            float4 v = *(const float4*)(B + (size_t)(k0 + kk) * ldb + n0 + nv * 4);
            *(float4*)&Bs[kk][nv * 4] = v;
        }
        __syncthreads();
        #pragma unroll
        for (int kk = 0; kk < BK; kk++) {
            float ra[TM], rb[TN];
            #pragma unroll
            for (int i = 0; i < TM; i++) ra[i] = As[kk][ty * TM + i];
            #pragma unroll
            for (int j = 0; j < TN; j++) rb[j] = Bs[kk][tx * TN + j];
            #pragma unroll
            for (int i = 0; i < TM; i++)
                #pragma unroll
                for (int j = 0; j < TN; j++) acc[i][j] = fmaf(ra[i], rb[j], acc[i][j]);
        }
        __syncthreads();
    }
    #pragma unroll
    for (int i = 0; i < TM; i++)
        #pragma unroll
        for (int j = 0; j < TN; j++) {
            float v = acc[i][j];
            if (rnd) v = tf32r(v);
            Cp[(size_t)(m0 + ty * TM + i) * ldc + n0 + tx * TN + j] = v;
        }
}

__global__ void y_k(const float* __restrict__ Xo, const float* __restrict__ lw,
                    const float* __restrict__ lb, const int* __restrict__ txp,
                    float* __restrict__ outy) {
    int id = blockIdx.x * blockDim.x + threadIdx.x;
    if (id >= NT * NUM_CLASS) return;
    int t = id / NUM_CLASS, k = id % NUM_CLASS;
    const float* xr = Xo + (size_t)txp[t] * 384;
    const float* wr = lw + (size_t)k * W_OUT;
    float s = 0.f;
    #pragma unroll 4
    for (int d = 0; d < W_OUT; d++) s = fmaf(xr[d], wr[d], s);
    outy[id] = s + lb[k];
}

__global__ void lossC_k(const float* __restrict__ y, const int* __restrict__ tgt,
                        float* __restrict__ part) {
    __shared__ float red[256];
    int t = blockIdx.x * 256 + threadIdx.x;
    float yv[NUM_CLASS];
    float m = -1e30f;
    #pragma unroll
    for (int k = 0; k < NUM_CLASS; k++) { yv[k] = y[t * NUM_CLASS + k]; m = fmaxf(m, yv[k]); }
    float se = 0.f;
    #pragma unroll
    for (int k = 0; k < NUM_CLASS; k++) se += expf(yv[k] - m);
    float lse = m + logf(se);
    red[threadIdx.x] = yv[tgt[t]] - lse;
    __syncthreads();
    for (int s = 128; s > 0; s >>= 1) {
        if (threadIdx.x < s) red[threadIdx.x] += red[threadIdx.x + s];
        __syncthreads();
    }
    if (threadIdx.x == 0) part[blockIdx.x] = red[0];
}

__global__ void lossR_k(const float* __restrict__ XORb, const float* __restrict__ X,
                        float* __restrict__ part) {
    __shared__ float red[256];
    const size_t total = (size_t)N * W_IN;
    size_t tid = (size_t)blockIdx.x * 256 + threadIdx.x;
    size_t stride = (size_t)gridDim.x * 256;
    float acc = 0.f;
    for (size_t i = tid; i < total; i += stride) {
        size_t row = i >> 8, col = i & 255;
        float x = XORb[row * 384 + 128 + col];
        if (x > 1.f || x < 0.f) x = 1.f / (1.f + expf(-x));
        float p = fminf(fmaxf(x, 1e-7f), 1.f - 1e-7f);
        float t = X[i];
        acc += t * logf(p) + (1.f - t) * log1pf(-p);
    }
    red[threadIdx.x] = acc;
    __syncthreads();
    for (int s = 128; s > 0; s >>= 1) {
        if (threadIdx.x < s) red[threadIdx.x] += red[threadIdx.x + s];
        __syncthreads();
    }
    if (threadIdx.x == 0) part[blockIdx.x] = red[0];
}

__global__ void final_k(const float* __restrict__ partR, const float* __restrict__ partC,
                        float* __restrict__ out) {
    __shared__ float red[256];
    red[threadIdx.x] = partR[threadIdx.x] + partR[threadIdx.x + 256];
    __syncthreads();
    for (int s = 128; s > 0; s >>= 1) {
        if (threadIdx.x < s) red[threadIdx.x] += red[threadIdx.x + s];
        __syncthreads();
    }
    if (threadIdx.x == 0) {
        float lossR = -red[0] / (float)((size_t)N * W_IN);
        float sC = partC[0] + partC[1] + partC[2] + partC[3];
        float lossC = -sC / (float)NT;
        out[0] = lossC + lossR;
        out[1 + NT * NUM_CLASS + 3 * C * E] = lossR;
    }
}

// ============================ host side ============================
constexpr int SMEM_NT = 2 * (128 * 36 + 32 * 136) * 4;   // 71680
constexpr int SMEM_TA = 2 * (32 * 136 + 32 * 136) * 4;   // 69632

extern "C" void kernel_launch(void* const* d_in, const int* in_sizes, int n_in,
                              void* d_out, int out_size) {
    float* S = nullptr;
    cudaGetSymbolAddress((void**)&S, g_scratch);

    const float* A   = (const float*)d_in[0];
    const float* X   = (const float*)d_in[1];
    const float* W   = (const float*)d_in[2];
    const float* W1  = (const float*)d_in[3];
    const float* W2  = (const float*)d_in[4];
    const float* lw  = (const float*)d_in[5];
    const float* lb  = (const float*)d_in[6];
    const float* w0a = (const float*)d_in[7];
    const float* w0b = (const float*)d_in[8];
    const float* w1a = (const float*)d_in[9];
    const int* txp   = (const int*)d_in[10];
    const int* tgt   = (const int*)d_in[11];
    float* out = (float*)d_out;

    cudaFuncSetAttribute(tgemm_k<false>, cudaFuncAttributeMaxDynamicSharedMemorySize, SMEM_NT);
    cudaFuncSetAttribute(tgemm_k<true>,  cudaFuncAttributeMaxDynamicSharedMemorySize, SMEM_TA);

    // 1. softmax weights + Ws outputs
    softmax_init_k<<<1, 32>>>(w0a, w0b, w1a, S + OFF_SW, out);
    // 2. a, b (tf32), a1 (raw)
    gtconv_k<<<(unsigned)(NN / 256), 256>>>(A, S + OFF_SW, S + OFF_A, S + OFF_B, S + OFF_A1);
    // 3. H = a @ b, diag->0, tf32
    tgemm_k<false><<<dim3(16, 16, 2), 256, SMEM_NT>>>(
        S + OFF_A, S + OFF_B, S + OFF_H, N, N, N, N, NN, NN, NN, 0, nullptr, 0, 2 | 8);
    // 4. cinv1 = 1/colsum(H)
    colsum_part_k<<<dim3(8, 16, 2), 256>>>(S + OFF_H, S + OFF_COLP, NN);
    cinv_fin_k<<<dim3(8, 1, 2), 256>>>(S + OFF_COLP, S + OFF_CI1);
    // 5. a1 <- tf32r(diag(cinv1) @ a1)  (in place)
    scale_a1_k<<<dim3(8, N, 2), 256>>>(S + OFF_A1, S + OFF_CI1);
    // 6. H2 = H @ a1n, diag->1, tf32   (colsum(H2 stored) == 1 + off-diag sum == ref degree)
    tgemm_k<false><<<dim3(16, 16, 2), 256, SMEM_NT>>>(
        S + OFF_H, S + OFF_A1, S + OFF_H2, N, N, N, N, NN, NN, NN, 0, nullptr, 0, 4 | 8);
    // 7. cinv2 = 1/colsum(H2 stored)
    colsum_part_k<<<dim3(8, 16, 2), 256>>>(S + OFF_H2, S + OFF_COLP, NN);
    cinv_fin_k<<<dim3(8, 1, 2), 256>>>(S + OFF_COLP, S + OFF_CI2);
    // 8. Hs = H2[0]+H2[1], diag->1; cinvs = 1/colsum(Hs)
    hsum_k<<<dim3(8, N), 256>>>(S + OFF_H2, S + OFF_HS);
    colsum_part_k<<<dim3(8, 16, 1), 256>>>(S + OFF_HS, S + OFF_COLP, 0);
    cinv_fin_k<<<dim3(8, 1, 1), 256>>>(S + OFF_COLP, S + OFF_CIS);
    // 9. XW = X @ W (tf32 at store)
    sgemm_k<64, 64, 16, 4, 4><<<dim3(2, 32), 256>>>(X, W, S + OFF_XW, W_IN, W_IN, 128, 128, 1);
    // 10. Xcat[:, z*128..] = relu(cinv2[z] * H2[z]^T @ XW)
    tgemm_k<true><<<dim3(1, 16, 2), 256, SMEM_TA>>>(
        S + OFF_H2, S + OFF_XW, S + OFF_XCAT, N, N, 128, 256, NN, 0, 0, 128,
        S + OFF_CI2, N, 1);
    // 11. Xcw = [Xcat@W1 | Xcat@W2]  (tf32)
    sgemm_k<64, 64, 16, 4, 4><<<dim3(2, 32), 256>>>(
        S + OFF_XCAT, W1, S + OFF_XCW, 256, 256, 128, 384, 1);
    sgemm_k<64, 64, 16, 4, 4><<<dim3(4, 32), 256>>>(
        S + OFF_XCAT, W2, S + OFF_XCW + 128, 256, 256, 256, 384, 1);
    // 12. XOR = cinvs * Hs^T @ Xcw   ([N,384]: Xo|Xr)
    tgemm_k<true><<<dim3(3, 16, 1), 256, SMEM_TA>>>(
        S + OFF_HS, S + OFF_XCW, S + OFF_XOR, N, N, 384, 384, 0, 0, 0, 0,
        S + OFF_CIS, 0, 0);
    // 13. y, losses, final
    y_k<<<(NT * NUM_CLASS) / 256, 256>>>(S + OFF_XOR, lw, lb, txp, out + 1);
    lossC_k<<<NT / 256, 256>>>(out + 1, tgt, S + OFF_PC);
    lossR_k<<<512, 256>>>(S + OFF_XOR, X, S + OFF_PR);
    final_k<<<1, 256>>>(S + OFF_PR, S + OFF_PC, out);
}

// round 9
// speedup vs baseline: 5.0153x; 1.6070x over previous
#include <cuda_runtime.h>
#include <cuda_fp16.h>
#include <math.h>
#include <stdint.h>

constexpr int N = 2048, E = 5, C = 2, W_IN = 256, W_OUT = 128, NUM_CLASS = 8, NT = 1024;
constexpr size_t NN = (size_t)N * (size_t)N;

// ---------------- half scratch ----------------
constexpr size_t HO_A    = 0;            // a [C,N,N]
constexpr size_t HO_B    = 2 * NN;       // b [C,N,N]
constexpr size_t HO_A1   = 4 * NN;       // a1; in-place cinv1-row-scaled
constexpr size_t HO_H    = 6 * NN;       // H diag->0
constexpr size_t HO_H2   = 8 * NN;       // H2 diag->1
constexpr size_t HO_XW   = 10 * NN;                      // [N,128]
constexpr size_t HO_XCAT = HO_XW   + (size_t)N * 128;    // [N,256]
constexpr size_t HO_XCW  = HO_XCAT + (size_t)N * 256;    // [N,384]
constexpr size_t H_TOTAL = HO_XCW  + (size_t)N * 384;

// ---------------- float scratch ----------------
constexpr size_t FO_XOR  = 0;                            // [N,384]
constexpr size_t FO_CI1  = FO_XOR + (size_t)N * 384;     // [C,N]
constexpr size_t FO_CI2  = FO_CI1 + (size_t)C * N;       // [C,N]
constexpr size_t FO_CIS  = FO_CI2 + (size_t)C * N;       // [N]
constexpr size_t FO_COLP = FO_CIS + N;                   // [2,16,N]
constexpr size_t FO_SW   = FO_COLP + (size_t)2 * 16 * N; // 30 (pad 32)
constexpr size_t FO_PR   = FO_SW + 32;                   // 512
constexpr size_t FO_PC   = FO_PR + 512;                  // 16
constexpr size_t F_TOTAL = FO_PC + 16;

__device__ __align__(1024) __half g_h[H_TOTAL];
__device__ __align__(1024) float  g_f[F_TOTAL];

// ============================ helpers ============================
__device__ __forceinline__ uint32_t smem_u32(const void* p) {
    uint32_t a;
    asm("{ .reg .u64 t; cvta.to.shared.u64 t, %1; cvt.u32.u64 %0, t; }" : "=r"(a) : "l"(p));
    return a;
}
__device__ __forceinline__ void cpa16(uint32_t saddr, const void* g) {
    asm volatile("cp.async.cg.shared.global [%0], [%1], 16;" :: "r"(saddr), "l"(g));
}
#define CP_COMMIT() asm volatile("cp.async.commit_group;" ::: "memory")

__device__ __forceinline__ void ldsm_x4(uint32_t* r, uint32_t a) {
    asm volatile("ldmatrix.sync.aligned.m8n8.x4.shared.b16 {%0,%1,%2,%3}, [%4];"
        : "=r"(r[0]), "=r"(r[1]), "=r"(r[2]), "=r"(r[3]) : "r"(a));
}
__device__ __forceinline__ void ldsm_x4t(uint32_t* r, uint32_t a) {
    asm volatile("ldmatrix.sync.aligned.m8n8.x4.trans.shared.b16 {%0,%1,%2,%3}, [%4];"
        : "=r"(r[0]), "=r"(r[1]), "=r"(r[2]), "=r"(r[3]) : "r"(a));
}
__device__ __forceinline__ void mma16816(float* d, const uint32_t* a, const uint32_t* b) {
    asm volatile(
        "mma.sync.aligned.m16n8k16.row.col.f32.f16.f16.f32 "
        "{%0,%1,%2,%3}, {%4,%5,%6,%7}, {%8,%9}, {%0,%1,%2,%3};"
        : "+f"(d[0]), "+f"(d[1]), "+f"(d[2]), "+f"(d[3])
        : "r"(a[0]), "r"(a[1]), "r"(a[2]), "r"(a[3]), "r"(b[0]), "r"(b[1]));
}

// ============================ fp16 tensor GEMM ============================
// C[m, coff+n] = rowsc[m] * (sum_k Aop[m,k]*B[k,n] [- B[m,n] if flag16])
//   TRANSA=false: Aop = A[m][k]. TRANSA=true: Aop = A[k][m].
//   SUMZ: accumulate over 2 z-planes of A (B shared), grid.z must be 1.
// flags: 1=relu, 2=diag->0, 4=diag->1, 16=subtract B row (diag corr), 32=f32 out
template <bool TRANSA, bool SUMZ>
__global__ void __launch_bounds__(256, 2)
hgemm_k(const __half* __restrict__ A, const __half* __restrict__ B, void* __restrict__ Cout,
        int K, int lda, int ldb, int ldc,
        size_t szA, size_t szB, size_t szC, int n_off,
        const float* __restrict__ rowsc, size_t sRow, int flags) {
    extern __shared__ __half sm[];
    constexpr int A_H = TRANSA ? 32 * 136 : 128 * 40;
    constexpr int B_H = 32 * 136;
    constexpr int STG = A_H + B_H;

    const int tid = threadIdx.x, lane = tid & 31, wid = tid >> 5;
    const int wm = wid >> 2, wn = wid & 3;
    const int m0 = blockIdx.y * 128, n0 = blockIdx.x * 128;
    const int z = SUMZ ? 0 : blockIdx.z;
    if (!SUMZ) { A += (size_t)z * szA; B += (size_t)z * szB; }
    const uint32_t sb = smem_u32(sm);

    float acc[4][4][4] = {};

    auto fillA = [&](int s, int zz, int k0) {
        uint32_t sa = sb + (uint32_t)s * STG * 2;
        const __half* Ap = SUMZ ? A + (size_t)zz * szA : A;
        #pragma unroll
        for (int e = 0; e < 2; e++) {
            int c = tid + e * 256;
            if (!TRANSA) {
                int m = c >> 2, ch = c & 3;
                cpa16(sa + (m * 40 + ch * 8) * 2, Ap + (size_t)(m0 + m) * lda + k0 + ch * 8);
            } else {
                int kk = c >> 4, ch = c & 15;
                cpa16(sa + (kk * 136 + ch * 8) * 2, Ap + (size_t)(k0 + kk) * lda + m0 + ch * 8);
            }
        }
        uint32_t sbb = sa + A_H * 2;
        #pragma unroll
        for (int e = 0; e < 2; e++) {
            int c = tid + e * 256;
            int kk = c >> 4, ch = c & 15;
            cpa16(sbb + (kk * 136 + ch * 8) * 2, B + (size_t)(k0 + kk) * ldb + n0 + ch * 8);
        }
        CP_COMMIT();
    };

    const int kit = K / 32;
    const int nit = SUMZ ? 2 * kit : kit;
    auto kz = [&](int kt, int& zz, int& k0) {
        if (SUMZ) { zz = kt / kit; k0 = (kt % kit) * 32; }
        else      { zz = 0;        k0 = kt * 32; }
    };

    { int zz, k0; kz(0, zz, k0); fillA(0, zz, k0); }
    if (nit > 1) { int zz, k0; kz(1, zz, k0); fillA(1, zz, k0); }

    for (int kt = 0; kt < nit; kt++) {
        if (kt + 2 < nit) {
            int zz, k0; kz(kt + 2, zz, k0);
            fillA((kt + 2) % 3, zz, k0);
            asm volatile("cp.async.wait_group 2;" ::: "memory");
        } else if (kt + 1 < nit) {
            asm volatile("cp.async.wait_group 1;" ::: "memory");
        } else {
            asm volatile("cp.async.wait_group 0;" ::: "memory");
        }
        __syncthreads();
        uint32_t sa = sb + (uint32_t)(kt % 3) * STG * 2;
        uint32_t sbs = sa + A_H * 2;
        #pragma unroll
        for (int ks = 0; ks < 2; ks++) {
            uint32_t af[4][4], bf[2][4];
            #pragma unroll
            for (int mt = 0; mt < 4; mt++) {
                if (!TRANSA) {
                    int row = wm * 64 + mt * 16 + (lane & 7) + ((lane >> 3) & 1) * 8;
                    int col = ks * 16 + (lane >> 4) * 8;
                    ldsm_x4(af[mt], sa + (row * 40 + col) * 2);
                } else {
                    int kr = ks * 16 + (lane & 7) + (lane >> 4) * 8;
                    int mc = wm * 64 + mt * 16 + ((lane >> 3) & 1) * 8;
                    ldsm_x4t(af[mt], sa + (kr * 136 + mc) * 2);
                }
            }
            #pragma unroll
            for (int np = 0; np < 2; np++) {
                int kr = ks * 16 + (lane & 7) + ((lane >> 3) & 1) * 8;
                int col = wn * 32 + np * 16 + (lane >> 4) * 8;
                ldsm_x4t(bf[np], sbs + (kr * 136 + col) * 2);
            }
            #pragma unroll
            for (int mt = 0; mt < 4; mt++)
                #pragma unroll
                for (int nt = 0; nt < 4; nt++)
                    mma16816(acc[mt][nt], af[mt], &bf[nt >> 1][(nt & 1) * 2]);
        }
        __syncthreads();
    }

    const int coff = z * n_off;
    #pragma unroll
    for (int mt = 0; mt < 4; mt++) {
        #pragma unroll
        for (int hf = 0; hf < 2; hf++) {
            int r = m0 + wm * 64 + mt * 16 + (lane >> 2) + hf * 8;
            float rs = rowsc ? rowsc[(size_t)z * sRow + r] : 1.f;
            #pragma unroll
            for (int nt = 0; nt < 4; nt++) {
                int cc = n0 + wn * 32 + nt * 8 + (lane & 3) * 2;
                float v0 = acc[mt][nt][hf * 2 + 0];
                float v1 = acc[mt][nt][hf * 2 + 1];
                if (flags & 16) {
                    v0 -= __half2float(B[(size_t)r * ldb + cc]);
                    v1 -= __half2float(B[(size_t)r * ldb + cc + 1]);
                }
                v0 *= rs; v1 *= rs;
                if (flags & 2) { if (r == cc) v0 = 0.f; if (r == cc + 1) v1 = 0.f; }
                if (flags & 4) { if (r == cc) v0 = 1.f; if (r == cc + 1) v1 = 1.f; }
                if (flags & 1) { v0 = fmaxf(v0, 0.f); v1 = fmaxf(v1, 0.f); }
                size_t off = (size_t)z * szC + (size_t)r * ldc + coff + cc;
                if (flags & 32) *(float2*)((float*)Cout + off) = make_float2(v0, v1);
                else *(__half2*)((__half*)Cout + off) = __floats2half2_rn(v0, v1);
            }
        }
    }
}

// ============================ small kernels ============================
__global__ void softmax_init_k(const float* __restrict__ w0a, const float* __restrict__ w0b,
                               const float* __restrict__ w1a, float* __restrict__ sw,
                               float* __restrict__ out) {
    int r = threadIdx.x;
    if (r < 3 * C) {
        int t = r >> 1, c = r & 1;
        const float* src = (t == 0) ? w0a : (t == 1) ? w0b : w1a;
        src += c * E;
        float v[E]; float m = -1e30f;
        #pragma unroll
        for (int e = 0; e < E; e++) { v[e] = src[e]; m = fmaxf(m, v[e]); }
        float s = 0.f;
        #pragma unroll
        for (int e = 0; e < E; e++) { v[e] = expf(v[e] - m); s += v[e]; }
        #pragma unroll
        for (int e = 0; e < E; e++) {
            float q = v[e] / s;
            sw[t * (C * E) + c * E + e] = q;
            out[1 + NT * NUM_CLASS + t * (C * E) + c * E + e] = q;
        }
    }
}

__global__ void gtconv_k(const float* __restrict__ A, const float* __restrict__ sw,
                         __half* __restrict__ pa, __half* __restrict__ pb,
                         __half* __restrict__ pa1) {
    size_t idx = (size_t)blockIdx.x * blockDim.x + threadIdx.x;
    if (idx >= NN) return;
    float av[E];
    #pragma unroll
    for (int e = 0; e < E; e++) av[e] = A[idx * E + e];
    #pragma unroll
    for (int c = 0; c < C; c++) {
        float sa = 0.f, sb = 0.f, s1 = 0.f;
        #pragma unroll
        for (int e = 0; e < E; e++) {
            sa = fmaf(sw[c * E + e], av[e], sa);
            sb = fmaf(sw[C * E + c * E + e], av[e], sb);
            s1 = fmaf(sw[2 * C * E + c * E + e], av[e], s1);
        }
        pa[c * NN + idx] = __float2half_rn(sa);
        pb[c * NN + idx] = __float2half_rn(sb);
        pa1[c * NN + idx] = __float2half_rn(s1);
    }
}

// a1[z][row][col] *= cinv1[z][row]  (in place, half2)
__global__ void scale_a1_k(__half* __restrict__ a1, const float* __restrict__ cinv1) {
    int col2 = (blockIdx.x * 256 + threadIdx.x) * 2;
    int row = blockIdx.y, z = blockIdx.z;
    size_t i = (size_t)z * NN + (size_t)row * N + col2;
    float sc = cinv1[z * N + row];
    __half2 h = *(__half2*)(a1 + i);
    float2 f = __half22float2(h);
    *(__half2*)(a1 + i) = __floats2half2_rn(f.x * sc, f.y * sc);
}

__global__ void colsum_part_h(const __half* __restrict__ H, float* __restrict__ part, size_t sH) {
    int col2 = (blockIdx.x * 256 + threadIdx.x) * 2;
    const __half* p = H + (size_t)blockIdx.z * sH + (size_t)blockIdx.y * 128 * N + col2;
    float s0 = 0.f, s1 = 0.f;
    #pragma unroll 8
    for (int i = 0; i < 128; i++) {
        float2 f = __half22float2(*(const __half2*)(p + (size_t)i * N));
        s0 += f.x; s1 += f.y;
    }
    float* dst = part + ((size_t)blockIdx.z * 16 + blockIdx.y) * N + col2;
    dst[0] = s0; dst[1] = s1;
}

__global__ void cinv_fin_k(const float* __restrict__ part, float* __restrict__ cinv) {
    int col = blockIdx.x * 256 + threadIdx.x;
    int z = blockIdx.z;
    float s = 0.f;
    #pragma unroll
    for (int r = 0; r < 16; r++) s += part[((size_t)z * 16 + r) * N + col];
    cinv[z * N + col] = (s == 0.f) ? 0.f : 1.f / s;
}

// cinv2[z] = 1/colsum(H2 stored); cinvs = 1/(s0+s1-1)
__global__ void fin2_k(const float* __restrict__ part, float* __restrict__ cinv2,
                       float* __restrict__ cinvs) {
    int col = blockIdx.x * 256 + threadIdx.x;
    float sz[2];
    #pragma unroll
    for (int z = 0; z < 2; z++) {
        float s = 0.f;
        #pragma unroll
        for (int r = 0; r < 16; r++) s += part[((size_t)z * 16 + r) * N + col];
        sz[z] = s;
        cinv2[z * N + col] = (s == 0.f) ? 0.f : 1.f / s;
    }
    float d = sz[0] + sz[1] - 1.f;
    cinvs[col] = (d == 0.f) ? 0.f : 1.f / d;
}

// SIMT GEMM, A generic (float/half), B float, out half
template <typename TA, int BM, int BN, int BK, int TM, int TN>
__global__ __launch_bounds__((BM / TM) * (BN / TN))
void sgemm_k(const TA* __restrict__ A, const float* __restrict__ B, __half* __restrict__ Cp,
             int K, int lda, int ldb, int ldc) {
    constexpr int NTHREADS = (BM / TM) * (BN / TN);
    __shared__ float As[BK][BM];
    __shared__ float Bs[BK][BN];
    const int tid = threadIdx.x;
    const int m0 = blockIdx.y * BM, n0 = blockIdx.x * BN;
    constexpr int TX = BN / TN;
    const int tx = tid % TX, ty = tid / TX;
    float acc[TM][TN];
    #pragma unroll
    for (int i = 0; i < TM; i++)
        #pragma unroll
        for (int j = 0; j < TN; j++) acc[i][j] = 0.f;
    for (int k0 = 0; k0 < K; k0 += BK) {
        constexpr int NA = (BM * BK) / NTHREADS;
        #pragma unroll
        for (int e = 0; e < NA; e++) {
            int idx = tid + e * NTHREADS;
            int mm = idx / BK, kk = idx % BK;
            As[kk][mm] = (float)A[(size_t)(m0 + mm) * lda + k0 + kk];
        }
        constexpr int NB = (BN * BK) / (NTHREADS * 4);
        #pragma unroll
        for (int e = 0; e < NB; e++) {
            int idx = tid + e * NTHREADS;
            int kk = idx / (BN / 4), nv = idx % (BN / 4);
            float4 v = *(const float4*)(B + (size_t)(k0 + kk) * ldb + n0 + nv * 4);
            *(float4*)&Bs[kk][nv * 4] = v;
        }
        __syncthreads();
        #pragma unroll
        for (int kk = 0; kk < BK; kk++) {
            float ra[TM], rb[TN];
            #pragma unroll
            for (int i = 0; i < TM; i++) ra[i] = As[kk][ty * TM + i];
            #pragma unroll
            for (int j = 0; j < TN; j++) rb[j] = Bs[kk][tx * TN + j];
            #pragma unroll
            for (int i = 0; i < TM; i++)
                #pragma unroll
                for (int j = 0; j < TN; j++) acc[i][j] = fmaf(ra[i], rb[j], acc[i][j]);
        }
        __syncthreads();
    }
    #pragma unroll
    for (int i = 0; i < TM; i++)
        #pragma unroll
        for (int j = 0; j < TN; j++)
            Cp[(size_t)(m0 + ty * TM + i) * ldc + n0 + tx * TN + j] =
                __float2half_rn(acc[i][j]);
}

__global__ void y_k(const float* __restrict__ Xo, const float* __restrict__ lw,
                    const float* __restrict__ lb, const int* __restrict__ txp,
                    float* __restrict__ outy) {
    int id = blockIdx.x * blockDim.x + threadIdx.x;
    if (id >= NT * NUM_CLASS) return;
    int t = id / NUM_CLASS, k = id % NUM_CLASS;
    const float* xr = Xo + (size_t)txp[t] * 384;
    const float* wr = lw + (size_t)k * W_OUT;
    float s = 0.f;
    #pragma unroll 4
    for (int d = 0; d < W_OUT; d++) s = fmaf(xr[d], wr[d], s);
    outy[id] = s + lb[k];
}

__global__ void lossC_k(const float* __restrict__ y, const int* __restrict__ tgt,
                        float* __restrict__ part) {
    __shared__ float red[256];
    int t = blockIdx.x * 256 + threadIdx.x;
    float yv[NUM_CLASS];
    float m = -1e30f;
    #pragma unroll
    for (int k = 0; k < NUM_CLASS; k++) { yv[k] = y[t * NUM_CLASS + k]; m = fmaxf(m, yv[k]); }
    float se = 0.f;
    #pragma unroll
    for (int k = 0; k < NUM_CLASS; k++) se += expf(yv[k] - m);
    float lse = m + logf(se);
    red[threadIdx.x] = yv[tgt[t]] - lse;
    __syncthreads();
    for (int s = 128; s > 0; s >>= 1) {
        if (threadIdx.x < s) red[threadIdx.x] += red[threadIdx.x + s];
        __syncthreads();
    }
    if (threadIdx.x == 0) part[blockIdx.x] = red[0];
}

__global__ void lossR_k(const float* __restrict__ XORb, const float* __restrict__ X,
                        float* __restrict__ part) {
    __shared__ float red[256];
    const size_t total = (size_t)N * W_IN;
    size_t tid = (size_t)blockIdx.x * 256 + threadIdx.x;
    size_t stride = (size_t)gridDim.x * 256;
    float acc = 0.f;
    for (size_t i = tid; i < total; i += stride) {
        size_t row = i >> 8, col = i & 255;
        float x = XORb[row * 384 + 128 + col];
        if (x > 1.f || x < 0.f) x = 1.f / (1.f + expf(-x));
        float p = fminf(fmaxf(x, 1e-7f), 1.f - 1e-7f);
        float t = X[i];
        acc += t * logf(p) + (1.f - t) * log1pf(-p);
    }
    red[threadIdx.x] = acc;
    __syncthreads();
    for (int s = 128; s > 0; s >>= 1) {
        if (threadIdx.x < s) red[threadIdx.x] += red[threadIdx.x + s];
        __syncthreads();
    }
    if (threadIdx.x == 0) part[blockIdx.x] = red[0];
}

__global__ void final_k(const float* __restrict__ partR, const float* __restrict__ partC,
                        float* __restrict__ out) {
    __shared__ float red[256];
    red[threadIdx.x] = partR[threadIdx.x] + partR[threadIdx.x + 256];
    __syncthreads();
    for (int s = 128; s > 0; s >>= 1) {
        if (threadIdx.x < s) red[threadIdx.x] += red[threadIdx.x + s];
        __syncthreads();
    }
    if (threadIdx.x == 0) {
        float lossR = -red[0] / (float)((size_t)N * W_IN);
        float sC = partC[0] + partC[1] + partC[2] + partC[3];
        float lossC = -sC / (float)NT;
        out[0] = lossC + lossR;
        out[1 + NT * NUM_CLASS + 3 * C * E] = lossR;
    }
}

// ============================ host side ============================
constexpr int SMEM_NT = (128 * 40 + 32 * 136) * 2 * 3;   // 56832
constexpr int SMEM_TA = (32 * 136 + 32 * 136) * 2 * 3;   // 52224

extern "C" void kernel_launch(void* const* d_in, const int* in_sizes, int n_in,
                              void* d_out, int out_size) {
    __half* Hh = nullptr;
    float* S = nullptr;
    cudaGetSymbolAddress((void**)&Hh, g_h);
    cudaGetSymbolAddress((void**)&S, g_f);

    const float* A   = (const float*)d_in[0];
    const float* X   = (const float*)d_in[1];
    const float* W   = (const float*)d_in[2];
    const float* W1  = (const float*)d_in[3];
    const float* W2  = (const float*)d_in[4];
    const float* lw  = (const float*)d_in[5];
    const float* lb  = (const float*)d_in[6];
    const float* w0a = (const float*)d_in[7];
    const float* w0b = (const float*)d_in[8];
    const float* w1a = (const float*)d_in[9];
    const int* txp   = (const int*)d_in[10];
    const int* tgt   = (const int*)d_in[11];
    float* out = (float*)d_out;

    cudaFuncSetAttribute((const void*)hgemm_k<false, false>,
                         cudaFuncAttributeMaxDynamicSharedMemorySize, SMEM_NT);
    cudaFuncSetAttribute((const void*)hgemm_k<true, false>,
                         cudaFuncAttributeMaxDynamicSharedMemorySize, SMEM_TA);
    cudaFuncSetAttribute((const void*)hgemm_k<true, true>,
                         cudaFuncAttributeMaxDynamicSharedMemorySize, SMEM_TA);

    // 1. softmax weights + Ws outputs
    softmax_init_k<<<1, 32>>>(w0a, w0b, w1a, S + FO_SW, out);
    // 2. a, b, a1 (fp16)
    gtconv_k<<<(unsigned)(NN / 256), 256>>>(A, S + FO_SW, Hh + HO_A, Hh + HO_B, Hh + HO_A1);
    // 3. H = a @ b, diag->0
    hgemm_k<false, false><<<dim3(16, 16, 2), 256, SMEM_NT>>>(
        Hh + HO_A, Hh + HO_B, Hh + HO_H, N, N, N, N, NN, NN, NN, 0, nullptr, 0, 2);
    // 4. cinv1 = 1/colsum(H)
    colsum_part_h<<<dim3(4, 16, 2), 256>>>(Hh + HO_H, S + FO_COLP, NN);
    cinv_fin_k<<<dim3(8, 1, 2), 256>>>(S + FO_COLP, S + FO_CI1);
    // 5. a1 <- diag(cinv1) @ a1  (in place)
    scale_a1_k<<<dim3(4, N, 2), 256>>>(Hh + HO_A1, S + FO_CI1);
    // 6. H2 = H @ a1n, diag->1
    hgemm_k<false, false><<<dim3(16, 16, 2), 256, SMEM_NT>>>(
        Hh + HO_H, Hh + HO_A1, Hh + HO_H2, N, N, N, N, NN, NN, NN, 0, nullptr, 0, 4);
    // 7. cinv2, cinvs from H2 colsums  (cinvs = 1/(s0+s1-1), no Hs needed)
    colsum_part_h<<<dim3(4, 16, 2), 256>>>(Hh + HO_H2, S + FO_COLP, NN);
    fin2_k<<<8, 256>>>(S + FO_COLP, S + FO_CI2, S + FO_CIS);
    // 8. XW = X @ W  (fp16 out)
    sgemm_k<float, 64, 64, 16, 4, 4><<<dim3(2, 32), 256>>>(X, W, Hh + HO_XW, W_IN, W_IN, 128, 128);
    // 9. Xcat[:, z*128..] = relu(cinv2[z] * H2[z]^T @ XW)
    hgemm_k<true, false><<<dim3(1, 16, 2), 256, SMEM_TA>>>(
        Hh + HO_H2, Hh + HO_XW, Hh + HO_XCAT, N, N, 128, 256, NN, 0, 0, 128,
        S + FO_CI2, N, 1);
    // 10. Xcw = [Xcat@W1 | Xcat@W2]  (fp16)
    sgemm_k<__half, 64, 64, 16, 4, 4><<<dim3(2, 32), 256>>>(
        Hh + HO_XCAT, W1, Hh + HO_XCW, 256, 256, 128, 384);
    sgemm_k<__half, 64, 64, 16, 4, 4><<<dim3(4, 32), 256>>>(
        Hh + HO_XCAT, W2, Hh + HO_XCW + 128, 256, 256, 256, 384);
    // 11. Xor = cinvs * (sum_z H2[z]^T @ Xcw - Xcw)   (f32 out)
    hgemm_k<true, true><<<dim3(3, 16, 1), 256, SMEM_TA>>>(
        Hh + HO_H2, Hh + HO_XCW, S + FO_XOR, N, N, 384, 384, NN, 0, 0, 0,
        S + FO_CIS, 0, 16 | 32);
    // 12. y, losses, final
    y_k<<<(NT * NUM_CLASS) / 256, 256>>>(S + FO_XOR, lw, lb, txp, out + 1);
    lossC_k<<<NT / 256, 256>>>(out + 1, tgt, S + FO_PC);
    lossR_k<<<512, 256>>>(S + FO_XOR, X, S + FO_PR);
    final_k<<<1, 256>>>(S + FO_PR, S + FO_PC, out);
}

// round 10
// speedup vs baseline: 5.6820x; 1.1329x over previous
#include <cuda_runtime.h>
#include <cuda_fp16.h>
#include <math.h>
#include <stdint.h>

constexpr int N = 2048, E = 5, C = 2, W_IN = 256, W_OUT = 128, NUM_CLASS = 8, NT = 1024;
constexpr size_t NN = (size_t)N * (size_t)N;

// ---------------- half scratch ----------------
constexpr size_t HO_A    = 0;            // a [C,N,N]
constexpr size_t HO_B    = 2 * NN;       // b [C,N,N]
constexpr size_t HO_A1   = 4 * NN;       // a1; in-place cinv1-row-scaled
constexpr size_t HO_H    = 6 * NN;       // H diag->0
constexpr size_t HO_H2   = 8 * NN;       // H2 diag->1
constexpr size_t HO_XW   = 10 * NN;                      // [N,128]
constexpr size_t HO_XCAT = HO_XW   + (size_t)N * 128;    // [N,256]
constexpr size_t HO_XCW  = HO_XCAT + (size_t)N * 256;    // [N,384]
constexpr size_t H_TOTAL = HO_XCW  + (size_t)N * 384;

// ---------------- float scratch ----------------
constexpr size_t FO_XOR  = 0;                             // [N,384]
constexpr size_t FO_CI1  = FO_XOR + (size_t)N * 384;      // [C,N]
constexpr size_t FO_CI2  = FO_CI1 + (size_t)C * N;        // [C,N]
constexpr size_t FO_CIS  = FO_CI2 + (size_t)C * N;        // [N]
constexpr size_t FO_COLP = FO_CIS + N;                    // [2,32,N]
constexpr size_t FO_SW   = FO_COLP + (size_t)2 * 32 * N;  // 30 (pad 32)
constexpr size_t FO_PR   = FO_SW + 32;                    // 512
constexpr size_t FO_PC   = FO_PR + 512;                   // 16
constexpr size_t FO_P    = FO_PC + 16;                    // split-K partials [4][N][384]
constexpr size_t F_TOTAL = FO_P + (size_t)4 * N * 384;

__device__ __align__(1024) __half g_h[H_TOTAL];
__device__ __align__(1024) float  g_f[F_TOTAL];

// ============================ helpers ============================
__device__ __forceinline__ uint32_t smem_u32(const void* p) {
    uint32_t a;
    asm("{ .reg .u64 t; cvta.to.shared.u64 t, %1; cvt.u32.u64 %0, t; }" : "=r"(a) : "l"(p));
    return a;
}
__device__ __forceinline__ void cpa16(uint32_t saddr, const void* g) {
    asm volatile("cp.async.cg.shared.global [%0], [%1], 16;" :: "r"(saddr), "l"(g));
}
#define CP_COMMIT() asm volatile("cp.async.commit_group;" ::: "memory")

__device__ __forceinline__ void ldsm_x4(uint32_t* r, uint32_t a) {
    asm volatile("ldmatrix.sync.aligned.m8n8.x4.shared.b16 {%0,%1,%2,%3}, [%4];"
        : "=r"(r[0]), "=r"(r[1]), "=r"(r[2]), "=r"(r[3]) : "r"(a));
}
__device__ __forceinline__ void ldsm_x4t(uint32_t* r, uint32_t a) {
    asm volatile("ldmatrix.sync.aligned.m8n8.x4.trans.shared.b16 {%0,%1,%2,%3}, [%4];"
        : "=r"(r[0]), "=r"(r[1]), "=r"(r[2]), "=r"(r[3]) : "r"(a));
}
__device__ __forceinline__ void mma16816(float* d, const uint32_t* a, const uint32_t* b) {
    asm volatile(
        "mma.sync.aligned.m16n8k16.row.col.f32.f16.f16.f32 "
        "{%0,%1,%2,%3}, {%4,%5,%6,%7}, {%8,%9}, {%0,%1,%2,%3};"
        : "+f"(d[0]), "+f"(d[1]), "+f"(d[2]), "+f"(d[3])
        : "r"(a[0]), "r"(a[1]), "r"(a[2]), "r"(a[3]), "r"(b[0]), "r"(b[1]));
}

// ============================ fp16 tensor GEMM (BK=64, 3-stage) ============================
// nsplit==1: C[m,n] = rowsc[m] * sum_k Aop[m,k]*B[k,n], half out, flags: 2=diag->0, 4=diag->1
// nsplit>1:  f32 partial per (z,split) written to pbuf + blockIdx.z*pstride, no epilogue
//   TRANSA: Aop = A[k][m].  SUMZ: K-space spans 2 z-planes of A (B shared).
template <bool TRANSA, bool SUMZ>
__global__ void __launch_bounds__(256, 2)
hgemm_k(const __half* __restrict__ A, const __half* __restrict__ B, __half* __restrict__ Cout,
        int K, int lda, int ldb, int ldc,
        size_t szA, size_t szB, size_t szC, int n_off,
        const float* __restrict__ rowsc, size_t sRow, int flags,
        int nsplit, float* __restrict__ pbuf, int ldp, size_t pstride) {
    extern __shared__ __half sm[];
    constexpr int A_H = TRANSA ? 64 * 136 : 128 * 72;
    constexpr int B_H = 64 * 136;
    constexpr int STG = A_H + B_H;

    const int tid = threadIdx.x, lane = tid & 31, wid = tid >> 5;
    const int wm = wid >> 2, wn = wid & 3;
    const int m0 = blockIdx.y * 128, n0 = blockIdx.x * 128;
    const int z = blockIdx.z / nsplit;
    const int split = blockIdx.z % nsplit;
    if (!SUMZ) { A += (size_t)z * szA; B += (size_t)z * szB; }
    const uint32_t sb = smem_u32(sm);

    float acc[4][4][4] = {};

    const int total_slabs = (SUMZ ? 2 * K : K) / 64;
    const int nit = total_slabs / nsplit;
    const int start = split * nit;

    auto fillA = [&](int s, int g) {
        int zz = SUMZ ? (g * 64) / K : 0;
        int k0 = SUMZ ? (g * 64) % K : g * 64;
        uint32_t sa = sb + (uint32_t)s * STG * 2;
        const __half* Ap = SUMZ ? A + (size_t)zz * szA : A;
        #pragma unroll
        for (int e = 0; e < 4; e++) {
            int c = tid + e * 256;
            if (!TRANSA) {
                int m = c >> 3, ch = c & 7;
                cpa16(sa + (m * 72 + ch * 8) * 2, Ap + (size_t)(m0 + m) * lda + k0 + ch * 8);
            } else {
                int kk = c >> 4, ch = c & 15;
                cpa16(sa + (kk * 136 + ch * 8) * 2, Ap + (size_t)(k0 + kk) * lda + m0 + ch * 8);
            }
        }
        uint32_t sbb = sa + A_H * 2;
        #pragma unroll
        for (int e = 0; e < 4; e++) {
            int c = tid + e * 256;
            int kk = c >> 4, ch = c & 15;
            cpa16(sbb + (kk * 136 + ch * 8) * 2, B + (size_t)(k0 + kk) * ldb + n0 + ch * 8);
        }
        CP_COMMIT();
    };

    fillA(0, start);
    fillA(1, start + 1);

    for (int j = 0; j < nit; j++) {
        if (j + 2 < nit) {
            fillA((j + 2) % 3, start + j + 2);
            asm volatile("cp.async.wait_group 2;" ::: "memory");
        } else if (j + 1 < nit) {
            asm volatile("cp.async.wait_group 1;" ::: "memory");
        } else {
            asm volatile("cp.async.wait_group 0;" ::: "memory");
        }
        __syncthreads();
        uint32_t sa = sb + (uint32_t)(j % 3) * STG * 2;
        uint32_t sbs = sa + A_H * 2;
        #pragma unroll
        for (int ks = 0; ks < 4; ks++) {
            uint32_t af[4][4], bf[2][4];
            #pragma unroll
            for (int mt = 0; mt < 4; mt++) {
                if (!TRANSA) {
                    int row = wm * 64 + mt * 16 + (lane & 7) + ((lane >> 3) & 1) * 8;
                    int col = ks * 16 + (lane >> 4) * 8;
                    ldsm_x4(af[mt], sa + (row * 72 + col) * 2);
                } else {
                    int kr = ks * 16 + (lane & 7) + (lane >> 4) * 8;
                    int mc = wm * 64 + mt * 16 + ((lane >> 3) & 1) * 8;
                    ldsm_x4t(af[mt], sa + (kr * 136 + mc) * 2);
                }
            }
            #pragma unroll
            for (int np = 0; np < 2; np++) {
                int kr = ks * 16 + (lane & 7) + ((lane >> 3) & 1) * 8;
                int col = wn * 32 + np * 16 + (lane >> 4) * 8;
                ldsm_x4t(bf[np], sbs + (kr * 136 + col) * 2);
            }
            #pragma unroll
            for (int mt = 0; mt < 4; mt++)
                #pragma unroll
                for (int nt = 0; nt < 4; nt++)
                    mma16816(acc[mt][nt], af[mt], &bf[nt >> 1][(nt & 1) * 2]);
        }
        __syncthreads();
    }

    if (nsplit > 1) {
        float* P = pbuf + (size_t)blockIdx.z * pstride;
        #pragma unroll
        for (int mt = 0; mt < 4; mt++)
            #pragma unroll
            for (int hf = 0; hf < 2; hf++) {
                int r = m0 + wm * 64 + mt * 16 + (lane >> 2) + hf * 8;
                #pragma unroll
                for (int nt = 0; nt < 4; nt++) {
                    int cc = n0 + wn * 32 + nt * 8 + (lane & 3) * 2;
                    *(float2*)(P + (size_t)r * ldp + cc) =
                        make_float2(acc[mt][nt][hf * 2], acc[mt][nt][hf * 2 + 1]);
                }
            }
        return;
    }

    const int coff = z * n_off;
    #pragma unroll
    for (int mt = 0; mt < 4; mt++) {
        #pragma unroll
        for (int hf = 0; hf < 2; hf++) {
            int r = m0 + wm * 64 + mt * 16 + (lane >> 2) + hf * 8;
            float rs = rowsc ? rowsc[(size_t)z * sRow + r] : 1.f;
            #pragma unroll
            for (int nt = 0; nt < 4; nt++) {
                int cc = n0 + wn * 32 + nt * 8 + (lane & 3) * 2;
                float v0 = acc[mt][nt][hf * 2 + 0] * rs;
                float v1 = acc[mt][nt][hf * 2 + 1] * rs;
                if (flags & 2) { if (r == cc) v0 = 0.f; if (r == cc + 1) v1 = 0.f; }
                if (flags & 4) { if (r == cc) v0 = 1.f; if (r == cc + 1) v1 = 1.f; }
                size_t off = (size_t)z * szC + (size_t)r * ldc + coff + cc;
                *(__half2*)(Cout + off) = __floats2half2_rn(v0, v1);
            }
        }
    }
}

// ============================ split-K combines ============================
// Xcat[r][z*128+c] = relu(ci2[z][r] * (P[2z][r][c] + P[2z+1][r][c]))
__global__ void comb9_k(const float* __restrict__ P, const float* __restrict__ ci2,
                        __half* __restrict__ Xcat) {
    int c = threadIdx.x;          // 0..127
    int r = blockIdx.x;           // 0..2047
    int z = blockIdx.y;           // 0..1
    size_t pi = (size_t)(z * 2) * N * 128 + (size_t)r * 128 + c;
    float v = P[pi] + P[pi + (size_t)N * 128];
    v = fmaxf(v * ci2[z * N + r], 0.f);
    Xcat[(size_t)r * 256 + z * 128 + c] = __float2half_rn(v);
}

// Xor[r][c] = cis[r] * (sum_s P[s][r][c] - Xcw[r][c])
__global__ void comb11_k(const float* __restrict__ P, const __half* __restrict__ Xcw,
                         const float* __restrict__ cis, float* __restrict__ Xor) {
    int c = blockIdx.y * 128 + threadIdx.x;   // 0..383
    int r = blockIdx.x;
    size_t i = (size_t)r * 384 + c;
    float s = 0.f;
    #pragma unroll
    for (int sp = 0; sp < 4; sp++) s += P[(size_t)sp * N * 384 + i];
    s -= __half2float(Xcw[i]);
    Xor[i] = s * cis[r];
}

// ============================ small kernels ============================
__global__ void softmax_init_k(const float* __restrict__ w0a, const float* __restrict__ w0b,
                               const float* __restrict__ w1a, float* __restrict__ sw,
                               float* __restrict__ out) {
    int r = threadIdx.x;
    if (r < 3 * C) {
        int t = r >> 1, c = r & 1;
        const float* src = (t == 0) ? w0a : (t == 1) ? w0b : w1a;
        src += c * E;
        float v[E]; float m = -1e30f;
        #pragma unroll
        for (int e = 0; e < E; e++) { v[e] = src[e]; m = fmaxf(m, v[e]); }
        float s = 0.f;
        #pragma unroll
        for (int e = 0; e < E; e++) { v[e] = expf(v[e] - m); s += v[e]; }
        #pragma unroll
        for (int e = 0; e < E; e++) {
            float q = v[e] / s;
            sw[t * (C * E) + c * E + e] = q;
            out[1 + NT * NUM_CLASS + t * (C * E) + c * E + e] = q;
        }
    }
}

// 4 indices per thread: 5x float4 in, uint2 (4 halves) out per array per channel
__global__ void gtconv_k(const float* __restrict__ A, const float* __restrict__ sw,
                         __half* __restrict__ pa, __half* __restrict__ pb,
                         __half* __restrict__ pa1) {
    size_t t = (size_t)blockIdx.x * blockDim.x + threadIdx.x;
    if (t * 4 >= NN) return;
    float v[20];
    const float4* Ap = (const float4*)(A + t * 20);
    #pragma unroll
    for (int q = 0; q < 5; q++) {
        float4 f = Ap[q];
        v[q * 4 + 0] = f.x; v[q * 4 + 1] = f.y; v[q * 4 + 2] = f.z; v[q * 4 + 3] = f.w;
    }
    #pragma unroll
    for (int c = 0; c < C; c++) {
        __half ha[4], hb[4], h1[4];
        #pragma unroll
        for (int g = 0; g < 4; g++) {
            float sa = 0.f, sb = 0.f, s1 = 0.f;
            #pragma unroll
            for (int e = 0; e < E; e++) {
                float av = v[g * 5 + e];
                sa = fmaf(sw[c * E + e], av, sa);
                sb = fmaf(sw[C * E + c * E + e], av, sb);
                s1 = fmaf(sw[2 * C * E + c * E + e], av, s1);
            }
            ha[g] = __float2half_rn(sa);
            hb[g] = __float2half_rn(sb);
            h1[g] = __float2half_rn(s1);
        }
        *(uint2*)(pa + c * NN + t * 4) = *(uint2*)ha;
        *(uint2*)(pb + c * NN + t * 4) = *(uint2*)hb;
        *(uint2*)(pa1 + c * NN + t * 4) = *(uint2*)h1;
    }
}

// a1[z][row][col8..+8] *= cinv1[z][row]  (in place)
__global__ void scale_a1_k(__half* __restrict__ a1, const float* __restrict__ cinv1) {
    int c8 = threadIdx.x * 8;
    int row = blockIdx.y, z = blockIdx.z;
    size_t i = (size_t)z * NN + (size_t)row * N + c8;
    float sc = cinv1[z * N + row];
    uint4 raw = *(uint4*)(a1 + i);
    __half2* h = (__half2*)&raw;
    #pragma unroll
    for (int q = 0; q < 4; q++) {
        float2 f = __half22float2(h[q]);
        h[q] = __floats2half2_rn(f.x * sc, f.y * sc);
    }
    *(uint4*)(a1 + i) = raw;
}

// column partial sums over 64-row chunks, 8 cols per thread (uint4 loads)
__global__ void colsum_part_h(const __half* __restrict__ H, float* __restrict__ part, size_t sH) {
    int c8 = threadIdx.x * 8;
    const __half* p = H + (size_t)blockIdx.z * sH + (size_t)blockIdx.y * 64 * N + c8;
    float s[8] = {};
    #pragma unroll 4
    for (int i = 0; i < 64; i++) {
        uint4 raw = *(const uint4*)(p + (size_t)i * N);
        const __half2* h = (const __half2*)&raw;
        #pragma unroll
        for (int q = 0; q < 4; q++) {
            float2 f = __half22float2(h[q]);
            s[q * 2] += f.x; s[q * 2 + 1] += f.y;
        }
    }
    float* dst = part + ((size_t)blockIdx.z * 32 + blockIdx.y) * N + c8;
    *(float4*)dst = make_float4(s[0], s[1], s[2], s[3]);
    *(float4*)(dst + 4) = make_float4(s[4], s[5], s[6], s[7]);
}

__global__ void cinv_fin_k(const float* __restrict__ part, float* __restrict__ cinv) {
    int col = blockIdx.x * 256 + threadIdx.x;
    int z = blockIdx.z;
    float s = 0.f;
    #pragma unroll
    for (int r = 0; r < 32; r++) s += part[((size_t)z * 32 + r) * N + col];
    cinv[z * N + col] = (s == 0.f) ? 0.f : 1.f / s;
}

// cinv2[z] = 1/colsum(H2 stored); cinvs = 1/(s0+s1-1)
__global__ void fin2_k(const float* __restrict__ part, float* __restrict__ cinv2,
                       float* __restrict__ cinvs) {
    int col = blockIdx.x * 256 + threadIdx.x;
    float sz[2];
    #pragma unroll
    for (int z = 0; z < 2; z++) {
        float s = 0.f;
        #pragma unroll
        for (int r = 0; r < 32; r++) s += part[((size_t)z * 32 + r) * N + col];
        sz[z] = s;
        cinv2[z * N + col] = (s == 0.f) ? 0.f : 1.f / s;
    }
    float d = sz[0] + sz[1] - 1.f;
    cinvs[col] = (d == 0.f) ? 0.f : 1.f / d;
}

// SIMT GEMM, A generic (float/half), B float, out half
template <typename TA, int BM, int BN, int BK, int TM, int TN>
__global__ __launch_bounds__((BM / TM) * (BN / TN))
void sgemm_k(const TA* __restrict__ A, const float* __restrict__ B, __half* __restrict__ Cp,
             int K, int lda, int ldb, int ldc) {
    constexpr int NTHREADS = (BM / TM) * (BN / TN);
    __shared__ float As[BK][BM];
    __shared__ float Bs[BK][BN];
    const int tid = threadIdx.x;
    const int m0 = blockIdx.y * BM, n0 = blockIdx.x * BN;
    constexpr int TX = BN / TN;
    const int tx = tid % TX, ty = tid / TX;
    float acc[TM][TN];
    #pragma unroll
    for (int i = 0; i < TM; i++)
        #pragma unroll
        for (int j = 0; j < TN; j++) acc[i][j] = 0.f;
    for (int k0 = 0; k0 < K; k0 += BK) {
        constexpr int NA = (BM * BK) / NTHREADS;
        #pragma unroll
        for (int e = 0; e < NA; e++) {
            int idx = tid + e * NTHREADS;
            int mm = idx / BK, kk = idx % BK;
            As[kk][mm] = (float)A[(size_t)(m0 + mm) * lda + k0 + kk];
        }
        constexpr int NB = (BN * BK) / (NTHREADS * 4);
        #pragma unroll
        for (int e = 0; e < NB; e++) {
            int idx = tid + e * NTHREADS;
            int kk = idx / (BN / 4), nv = idx % (BN / 4);
            float4 v = *(const float4*)(B + (size_t)(k0 + kk) * ldb + n0 + nv * 4);
            *(float4*)&Bs[kk][nv * 4] = v;
        }
        __syncthreads();
        #pragma unroll
        for (int kk = 0; kk < BK; kk++) {
            float ra[TM], rb[TN];
            #pragma unroll
            for (int i = 0; i < TM; i++) ra[i] = As[kk][ty * TM + i];
            #pragma unroll
            for (int j = 0; j < TN; j++) rb[j] = Bs[kk][tx * TN + j];
            #pragma unroll
            for (int i = 0; i < TM; i++)
                #pragma unroll
                for (int j = 0; j < TN; j++) acc[i][j] = fmaf(ra[i], rb[j], acc[i][j]);
        }
        __syncthreads();
    }
    #pragma unroll
    for (int i = 0; i < TM; i++)
        #pragma unroll
        for (int j = 0; j < TN; j++)
            Cp[(size_t)(m0 + ty * TM + i) * ldc + n0 + tx * TN + j] =
                __float2half_rn(acc[i][j]);
}

__global__ void y_k(const float* __restrict__ Xo, const float* __restrict__ lw,
                    const float* __restrict__ lb, const int* __restrict__ txp,
                    float* __restrict__ outy) {
    int id = blockIdx.x * blockDim.x + threadIdx.x;
    if (id >= NT * NUM_CLASS) return;
    int t = id / NUM_CLASS, k = id % NUM_CLASS;
    const float* xr = Xo + (size_t)txp[t] * 384;
    const float* wr = lw + (size_t)k * W_OUT;
    float s = 0.f;
    #pragma unroll 4
    for (int d = 0; d < W_OUT; d++) s = fmaf(xr[d], wr[d], s);
    outy[id] = s + lb[k];
}

__global__ void lossC_k(const float* __restrict__ y, const int* __restrict__ tgt,
                        float* __restrict__ part) {
    __shared__ float red[256];
    int t = blockIdx.x * 256 + threadIdx.x;
    float yv[NUM_CLASS];
    float m = -1e30f;
    #pragma unroll
    for (int k = 0; k < NUM_CLASS; k++) { yv[k] = y[t * NUM_CLASS + k]; m = fmaxf(m, yv[k]); }
    float se = 0.f;
    #pragma unroll
    for (int k = 0; k < NUM_CLASS; k++) se += expf(yv[k] - m);
    float lse = m + logf(se);
    red[threadIdx.x] = yv[tgt[t]] - lse;
    __syncthreads();
    for (int s = 128; s > 0; s >>= 1) {
        if (threadIdx.x < s) red[threadIdx.x] += red[threadIdx.x + s];
        __syncthreads();
    }
    if (threadIdx.x == 0) part[blockIdx.x] = red[0];
}

__global__ void lossR_k(const float* __restrict__ XORb, const float* __restrict__ X,
                        float* __restrict__ part) {
    __shared__ float red[256];
    const size_t total = (size_t)N * W_IN;
    size_t tid = (size_t)blockIdx.x * 256 + threadIdx.x;
    size_t stride = (size_t)gridDim.x * 256;
    float acc = 0.f;
    for (size_t i = tid; i < total; i += stride) {
        size_t row = i >> 8, col = i & 255;
        float x = XORb[row * 384 + 128 + col];
        if (x > 1.f || x < 0.f) x = 1.f / (1.f + expf(-x));
        float p = fminf(fmaxf(x, 1e-7f), 1.f - 1e-7f);
        float t = X[i];
        acc += t * logf(p) + (1.f - t) * log1pf(-p);
    }
    red[threadIdx.x] = acc;
    __syncthreads();
    for (int s = 128; s > 0; s >>= 1) {
        if (threadIdx.x < s) red[threadIdx.x] += red[threadIdx.x + s];
        __syncthreads();
    }
    if (threadIdx.x == 0) part[blockIdx.x] = red[0];
}

__global__ void final_k(const float* __restrict__ partR, const float* __restrict__ partC,
                        float* __restrict__ out) {
    __shared__ float red[256];
    red[threadIdx.x] = partR[threadIdx.x] + partR[threadIdx.x + 256];
    __syncthreads();
    for (int s = 128; s > 0; s >>= 1) {
        if (threadIdx.x < s) red[threadIdx.x] += red[threadIdx.x + s];
        __syncthreads();
    }
    if (threadIdx.x == 0) {
        float lossR = -red[0] / (float)((size_t)N * W_IN);
        float sC = partC[0] + partC[1] + partC[2] + partC[3];
        float lossC = -sC / (float)NT;
        out[0] = lossC + lossR;
        out[1 + NT * NUM_CLASS + 3 * C * E] = lossR;
    }
}

// ============================ host side ============================
constexpr int SMEM_NT = (128 * 72 + 64 * 136) * 2 * 3;   // 107520
constexpr int SMEM_TA = (64 * 136 + 64 * 136) * 2 * 3;   // 104448

extern "C" void kernel_launch(void* const* d_in, const int* in_sizes, int n_in,
                              void* d_out, int out_size) {
    __half* Hh = nullptr;
    float* S = nullptr;
    cudaGetSymbolAddress((void**)&Hh, g_h);
    cudaGetSymbolAddress((void**)&S, g_f);

    const float* A   = (const float*)d_in[0];
    const float* X   = (const float*)d_in[1];
    const float* W   = (const float*)d_in[2];
    const float* W1  = (const float*)d_in[3];
    const float* W2  = (const float*)d_in[4];
    const float* lw  = (const float*)d_in[5];
    const float* lb  = (const float*)d_in[6];
    const float* w0a = (const float*)d_in[7];
    const float* w0b = (const float*)d_in[8];
    const float* w1a = (const float*)d_in[9];
    const int* txp   = (const int*)d_in[10];
    const int* tgt   = (const int*)d_in[11];
    float* out = (float*)d_out;

    cudaFuncSetAttribute((const void*)hgemm_k<false, false>,
                         cudaFuncAttributeMaxDynamicSharedMemorySize, SMEM_NT);
    cudaFuncSetAttribute((const void*)hgemm_k<true, false>,
                         cudaFuncAttributeMaxDynamicSharedMemorySize, SMEM_TA);
    cudaFuncSetAttribute((const void*)hgemm_k<true, true>,
                         cudaFuncAttributeMaxDynamicSharedMemorySize, SMEM_TA);

    // 1. softmax weights + Ws outputs
    softmax_init_k<<<1, 32>>>(w0a, w0b, w1a, S + FO_SW, out);
    // 2. a, b, a1 (fp16)
    gtconv_k<<<(unsigned)(NN / 4 / 256), 256>>>(A, S + FO_SW, Hh + HO_A, Hh + HO_B, Hh + HO_A1);
    // 3. H = a @ b, diag->0
    hgemm_k<false, false><<<dim3(16, 16, 2), 256, SMEM_NT>>>(
        Hh + HO_A, Hh + HO_B, Hh + HO_H, N, N, N, N, NN, NN, NN, 0, nullptr, 0, 2,
        1, nullptr, 0, 0);
    // 4. cinv1 = 1/colsum(H)
    colsum_part_h<<<dim3(1, 32, 2), 256>>>(Hh + HO_H, S + FO_COLP, NN);
    cinv_fin_k<<<dim3(8, 1, 2), 256>>>(S + FO_COLP, S + FO_CI1);
    // 5. a1 <- diag(cinv1) @ a1  (in place)
    scale_a1_k<<<dim3(1, N, 2), 256>>>(Hh + HO_A1, S + FO_CI1);
    // 6. H2 = H @ a1n, diag->1
    hgemm_k<false, false><<<dim3(16, 16, 2), 256, SMEM_NT>>>(
        Hh + HO_H, Hh + HO_A1, Hh + HO_H2, N, N, N, N, NN, NN, NN, 0, nullptr, 0, 4,
        1, nullptr, 0, 0);
    // 7. cinv2, cinvs from H2 colsums  (cinvs = 1/(s0+s1-1))
    colsum_part_h<<<dim3(1, 32, 2), 256>>>(Hh + HO_H2, S + FO_COLP, NN);
    fin2_k<<<8, 256>>>(S + FO_COLP, S + FO_CI2, S + FO_CIS);
    // 8. XW = X @ W  (fp16 out)
    sgemm_k<float, 64, 64, 16, 4, 4><<<dim3(2, 32), 256>>>(X, W, Hh + HO_XW, W_IN, W_IN, 128, 128);
    // 9. P[z*2+s] = (H2[z]^T @ XW) k-split partials; combine -> Xcat
    hgemm_k<true, false><<<dim3(1, 16, 4), 256, SMEM_TA>>>(
        Hh + HO_H2, Hh + HO_XW, nullptr, N, N, 128, 0, NN, 0, 0, 0, nullptr, 0, 0,
        2, S + FO_P, 128, (size_t)N * 128);
    comb9_k<<<dim3(N, 2), 128>>>(S + FO_P, S + FO_CI2, Hh + HO_XCAT);
    // 10. Xcw = [Xcat@W1 | Xcat@W2]  (fp16)
    sgemm_k<__half, 64, 64, 16, 4, 4><<<dim3(2, 32), 256>>>(
        Hh + HO_XCAT, W1, Hh + HO_XCW, 256, 256, 128, 384);
    sgemm_k<__half, 64, 64, 16, 4, 4><<<dim3(4, 32), 256>>>(
        Hh + HO_XCAT, W2, Hh + HO_XCW + 128, 256, 256, 256, 384);
    // 11. P[s] = partial sums of (sum_z H2[z]^T @ Xcw); combine -> Xor (f32)
    hgemm_k<true, true><<<dim3(3, 16, 4), 256, SMEM_TA>>>(
        Hh + HO_H2, Hh + HO_XCW, nullptr, N, N, 384, 0, NN, 0, 0, 0, nullptr, 0, 0,
        4, S + FO_P, 384, (size_t)N * 384);
    comb11_k<<<dim3(N, 3), 128>>>(S + FO_P, Hh + HO_XCW, S + FO_CIS, S + FO_XOR);
    // 12. y, losses, final
    y_k<<<(NT * NUM_CLASS) / 256, 256>>>(S + FO_XOR, lw, lb, txp, out + 1);
    lossC_k<<<NT / 256, 256>>>(out + 1, tgt, S + FO_PC);
    lossR_k<<<512, 256>>>(S + FO_XOR, X, S + FO_PR);
    final_k<<<1, 256>>>(S + FO_PR, S + FO_PC, out);
}

// round 11
// speedup vs baseline: 6.5030x; 1.1445x over previous
#include <cuda_runtime.h>
#include <cuda_fp16.h>
#include <math.h>
#include <stdint.h>

constexpr int N = 2048, E = 5, C = 2, W_IN = 256, W_OUT = 128, NUM_CLASS = 8, NT = 1024;
constexpr size_t NN = (size_t)N * (size_t)N;

// ---------------- half scratch ----------------
constexpr size_t HO_A    = 0;            // a [C,N,N]
constexpr size_t HO_B    = 2 * NN;       // b [C,N,N]
constexpr size_t HO_A1   = 4 * NN;       // a1; in-place cinv1-row-scaled
constexpr size_t HO_H    = 6 * NN;       // H diag->0
constexpr size_t HO_H2   = 8 * NN;       // H2 diag->1
constexpr size_t HO_XW   = 10 * NN;                      // [N,128]
constexpr size_t HO_XCAT = HO_XW   + (size_t)N * 128;    // [N,256]
constexpr size_t HO_XCW  = HO_XCAT + (size_t)N * 256;    // [N,384]
constexpr size_t HO_XH   = HO_XCW  + (size_t)N * 384;    // X as fp16 [N,256]
constexpr size_t HO_WF   = HO_XH   + (size_t)N * 256;    // [W1|W2] fp16 [256,384]
constexpr size_t H_TOTAL = HO_WF   + (size_t)256 * 384;

// ---------------- float scratch ----------------
constexpr size_t FO_XOR  = 0;                             // [N,384]
constexpr size_t FO_CI1  = FO_XOR + (size_t)N * 384;      // [C,N]
constexpr size_t FO_CI2  = FO_CI1 + (size_t)C * N;        // [C,N]
constexpr size_t FO_CIS  = FO_CI2 + (size_t)C * N;        // [N]
constexpr size_t FO_COLP = FO_CIS + N;                    // [2,64,N]
constexpr size_t FO_SW   = FO_COLP + (size_t)2 * 64 * N;  // 30 (pad 32)
constexpr size_t FO_PR   = FO_SW + 32;                    // 512
constexpr size_t FO_PC   = FO_PR + 512;                   // 16
constexpr size_t FO_P    = FO_PC + 16;                    // split-K partials [4][N][384]
constexpr size_t F_TOTAL = FO_P + (size_t)4 * N * 384;

__device__ __align__(1024) __half g_h[H_TOTAL];
__device__ __align__(1024) float  g_f[F_TOTAL];

// ============================ helpers ============================
__device__ __forceinline__ uint32_t smem_u32(const void* p) {
    uint32_t a;
    asm("{ .reg .u64 t; cvta.to.shared.u64 t, %1; cvt.u32.u64 %0, t; }" : "=r"(a) : "l"(p));
    return a;
}
__device__ __forceinline__ void cpa16(uint32_t saddr, const void* g) {
    asm volatile("cp.async.cg.shared.global [%0], [%1], 16;" :: "r"(saddr), "l"(g));
}
#define CP_COMMIT() asm volatile("cp.async.commit_group;" ::: "memory")

__device__ __forceinline__ void ldsm_x4(uint32_t* r, uint32_t a) {
    asm volatile("ldmatrix.sync.aligned.m8n8.x4.shared.b16 {%0,%1,%2,%3}, [%4];"
        : "=r"(r[0]), "=r"(r[1]), "=r"(r[2]), "=r"(r[3]) : "r"(a));
}
__device__ __forceinline__ void ldsm_x4t(uint32_t* r, uint32_t a) {
    asm volatile("ldmatrix.sync.aligned.m8n8.x4.trans.shared.b16 {%0,%1,%2,%3}, [%4];"
        : "=r"(r[0]), "=r"(r[1]), "=r"(r[2]), "=r"(r[3]) : "r"(a));
}
__device__ __forceinline__ void mma16816(float* d, const uint32_t* a, const uint32_t* b) {
    asm volatile(
        "mma.sync.aligned.m16n8k16.row.col.f32.f16.f16.f32 "
        "{%0,%1,%2,%3}, {%4,%5,%6,%7}, {%8,%9}, {%0,%1,%2,%3};"
        : "+f"(d[0]), "+f"(d[1]), "+f"(d[2]), "+f"(d[3])
        : "r"(a[0]), "r"(a[1]), "r"(a[2]), "r"(a[3]), "r"(b[0]), "r"(b[1]));
}

// ============================ fp16 tensor GEMM (BK=64, 3-stage, 1 sync/slab) ============================
// nsplit==1: C[m,n] = rowsc[m] * sum_k Aop[m,k]*B[k,n], half out, flags: 2=diag->0, 4=diag->1
// nsplit>1:  f32 partial per (z,split) written to pbuf + blockIdx.z*pstride, no epilogue
//   TRANSA: Aop = A[k][m].  SUMZ: K-space spans 2 z-planes of A (B shared).
template <bool TRANSA, bool SUMZ>
__global__ void __launch_bounds__(256, 2)
hgemm_k(const __half* __restrict__ A, const __half* __restrict__ B, __half* __restrict__ Cout,
        int K, int lda, int ldb, int ldc,
        size_t szA, size_t szB, size_t szC, int n_off,
        const float* __restrict__ rowsc, size_t sRow, int flags,
        int nsplit, float* __restrict__ pbuf, int ldp, size_t pstride) {
    extern __shared__ __half sm[];
    constexpr int A_H = TRANSA ? 64 * 136 : 128 * 72;
    constexpr int B_H = 64 * 136;
    constexpr int STG = A_H + B_H;

    const int tid = threadIdx.x, lane = tid & 31, wid = tid >> 5;
    const int wm = wid >> 2, wn = wid & 3;
    const int m0 = blockIdx.y * 128, n0 = blockIdx.x * 128;
    const int z = blockIdx.z / nsplit;
    const int split = blockIdx.z % nsplit;
    if (!SUMZ) { A += (size_t)z * szA; B += (size_t)z * szB; }
    const uint32_t sb = smem_u32(sm);

    float acc[4][4][4] = {};

    const int total_slabs = (SUMZ ? 2 * K : K) / 64;
    const int nit = total_slabs / nsplit;
    const int start = split * nit;

    auto fillA = [&](int s, int g) {
        int zz = SUMZ ? (g * 64) / K : 0;
        int k0 = SUMZ ? (g * 64) % K : g * 64;
        uint32_t sa = sb + (uint32_t)s * STG * 2;
        const __half* Ap = SUMZ ? A + (size_t)zz * szA : A;
        #pragma unroll
        for (int e = 0; e < 4; e++) {
            int c = tid + e * 256;
            if (!TRANSA) {
                int m = c >> 3, ch = c & 7;
                cpa16(sa + (m * 72 + ch * 8) * 2, Ap + (size_t)(m0 + m) * lda + k0 + ch * 8);
            } else {
                int kk = c >> 4, ch = c & 15;
                cpa16(sa + (kk * 136 + ch * 8) * 2, Ap + (size_t)(k0 + kk) * lda + m0 + ch * 8);
            }
        }
        uint32_t sbb = sa + A_H * 2;
        #pragma unroll
        for (int e = 0; e < 4; e++) {
            int c = tid + e * 256;
            int kk = c >> 4, ch = c & 15;
            cpa16(sbb + (kk * 136 + ch * 8) * 2, B + (size_t)(k0 + kk) * ldb + n0 + ch * 8);
        }
        CP_COMMIT();
    };

    fillA(0, start);
    fillA(1, start + 1);

    for (int j = 0; j < nit; j++) {
        if (j + 1 < nit) asm volatile("cp.async.wait_group 1;" ::: "memory");
        else             asm volatile("cp.async.wait_group 0;" ::: "memory");
        __syncthreads();
        if (j + 2 < nit) fillA((j + 2) % 3, start + j + 2);
        uint32_t sa = sb + (uint32_t)(j % 3) * STG * 2;
        uint32_t sbs = sa + A_H * 2;
        #pragma unroll
        for (int ks = 0; ks < 4; ks++) {
            uint32_t af[4][4], bf[2][4];
            #pragma unroll
            for (int mt = 0; mt < 4; mt++) {
                if (!TRANSA) {
                    int row = wm * 64 + mt * 16 + (lane & 7) + ((lane >> 3) & 1) * 8;
                    int col = ks * 16 + (lane >> 4) * 8;
                    ldsm_x4(af[mt], sa + (row * 72 + col) * 2);
                } else {
                    int kr = ks * 16 + (lane & 7) + (lane >> 4) * 8;
                    int mc = wm * 64 + mt * 16 + ((lane >> 3) & 1) * 8;
                    ldsm_x4t(af[mt], sa + (kr * 136 + mc) * 2);
                }
            }
            #pragma unroll
            for (int np = 0; np < 2; np++) {
                int kr = ks * 16 + (lane & 7) + ((lane >> 3) & 1) * 8;
                int col = wn * 32 + np * 16 + (lane >> 4) * 8;
                ldsm_x4t(bf[np], sbs + (kr * 136 + col) * 2);
            }
            #pragma unroll
            for (int mt = 0; mt < 4; mt++)
                #pragma unroll
                for (int nt = 0; nt < 4; nt++)
                    mma16816(acc[mt][nt], af[mt], &bf[nt >> 1][(nt & 1) * 2]);
        }
    }

    if (nsplit > 1) {
        float* P = pbuf + (size_t)blockIdx.z * pstride;
        #pragma unroll
        for (int mt = 0; mt < 4; mt++)
            #pragma unroll
            for (int hf = 0; hf < 2; hf++) {
                int r = m0 + wm * 64 + mt * 16 + (lane >> 2) + hf * 8;
                #pragma unroll
                for (int nt = 0; nt < 4; nt++) {
                    int cc = n0 + wn * 32 + nt * 8 + (lane & 3) * 2;
                    *(float2*)(P + (size_t)r * ldp + cc) =
                        make_float2(acc[mt][nt][hf * 2], acc[mt][nt][hf * 2 + 1]);
                }
            }
        return;
    }

    const int coff = z * n_off;
    #pragma unroll
    for (int mt = 0; mt < 4; mt++) {
        #pragma unroll
        for (int hf = 0; hf < 2; hf++) {
            int r = m0 + wm * 64 + mt * 16 + (lane >> 2) + hf * 8;
            float rs = rowsc ? rowsc[(size_t)z * sRow + r] : 1.f;
            #pragma unroll
            for (int nt = 0; nt < 4; nt++) {
                int cc = n0 + wn * 32 + nt * 8 + (lane & 3) * 2;
                float v0 = acc[mt][nt][hf * 2 + 0] * rs;
                float v1 = acc[mt][nt][hf * 2 + 1] * rs;
                if (flags & 2) { if (r == cc) v0 = 0.f; if (r == cc + 1) v1 = 0.f; }
                if (flags & 4) { if (r == cc) v0 = 1.f; if (r == cc + 1) v1 = 1.f; }
                size_t off = (size_t)z * szC + (size_t)r * ldc + coff + cc;
                *(__half2*)(Cout + off) = __floats2half2_rn(v0, v1);
            }
        }
    }
}

// ============================ split-K combines ============================
__global__ void comb9_k(const float* __restrict__ P, const float* __restrict__ ci2,
                        __half* __restrict__ Xcat) {
    int c = threadIdx.x;
    int r = blockIdx.x;
    int z = blockIdx.y;
    size_t pi = (size_t)(z * 2) * N * 128 + (size_t)r * 128 + c;
    float v = P[pi] + P[pi + (size_t)N * 128];
    v = fmaxf(v * ci2[z * N + r], 0.f);
    Xcat[(size_t)r * 256 + z * 128 + c] = __float2half_rn(v);
}

__global__ void comb11_k(const float* __restrict__ P, const __half* __restrict__ Xcw,
                         const float* __restrict__ cis, float* __restrict__ Xor) {
    int c = blockIdx.y * 128 + threadIdx.x;
    int r = blockIdx.x;
    size_t i = (size_t)r * 384 + c;
    float s = 0.f;
    #pragma unroll
    for (int sp = 0; sp < 4; sp++) s += P[(size_t)sp * N * 384 + i];
    s -= __half2float(Xcw[i]);
    Xor[i] = s * cis[r];
}

// ============================ small kernels ============================
__global__ void softmax_init_k(const float* __restrict__ w0a, const float* __restrict__ w0b,
                               const float* __restrict__ w1a, float* __restrict__ sw,
                               float* __restrict__ out) {
    int r = threadIdx.x;
    if (r < 3 * C) {
        int t = r >> 1, c = r & 1;
        const float* src = (t == 0) ? w0a : (t == 1) ? w0b : w1a;
        src += c * E;
        float v[E]; float m = -1e30f;
        #pragma unroll
        for (int e = 0; e < E; e++) { v[e] = src[e]; m = fmaxf(m, v[e]); }
        float s = 0.f;
        #pragma unroll
        for (int e = 0; e < E; e++) { v[e] = expf(v[e] - m); s += v[e]; }
        #pragma unroll
        for (int e = 0; e < E; e++) {
            float q = v[e] / s;
            sw[t * (C * E) + c * E + e] = q;
            out[1 + NT * NUM_CLASS + t * (C * E) + c * E + e] = q;
        }
    }
}

__global__ void gtconv_k(const float* __restrict__ A, const float* __restrict__ sw,
                         __half* __restrict__ pa, __half* __restrict__ pb,
                         __half* __restrict__ pa1) {
    size_t t = (size_t)blockIdx.x * blockDim.x + threadIdx.x;
    if (t * 4 >= NN) return;
    float v[20];
    const float4* Ap = (const float4*)(A + t * 20);
    #pragma unroll
    for (int q = 0; q < 5; q++) {
        float4 f = Ap[q];
        v[q * 4 + 0] = f.x; v[q * 4 + 1] = f.y; v[q * 4 + 2] = f.z; v[q * 4 + 3] = f.w;
    }
    #pragma unroll
    for (int c = 0; c < C; c++) {
        __half ha[4], hb[4], h1[4];
        #pragma unroll
        for (int g = 0; g < 4; g++) {
            float sa = 0.f, sb = 0.f, s1 = 0.f;
            #pragma unroll
            for (int e = 0; e < E; e++) {
                float av = v[g * 5 + e];
                sa = fmaf(sw[c * E + e], av, sa);
                sb = fmaf(sw[C * E + c * E + e], av, sb);
                s1 = fmaf(sw[2 * C * E + c * E + e], av, s1);
            }
            ha[g] = __float2half_rn(sa);
            hb[g] = __float2half_rn(sb);
            h1[g] = __float2half_rn(s1);
        }
        *(uint2*)(pa + c * NN + t * 4) = *(uint2*)ha;
        *(uint2*)(pb + c * NN + t * 4) = *(uint2*)hb;
        *(uint2*)(pa1 + c * NN + t * 4) = *(uint2*)h1;
    }
}

// X -> fp16 Xh (blocks 0..255); [W1|W2] -> fp16 Wf (blocks 256..303)
__global__ void convh_k(const float* __restrict__ X, const float* __restrict__ W1,
                        const float* __restrict__ W2, __half* __restrict__ Xh,
                        __half* __restrict__ Wf) {
    int b = blockIdx.x;
    if (b < 256) {
        size_t base = (size_t)b * 2048 + threadIdx.x * 8;
        const float4* src = (const float4*)(X + base);
        __half h[8];
        float4 f0 = src[0], f1 = src[1];
        h[0] = __float2half_rn(f0.x); h[1] = __float2half_rn(f0.y);
        h[2] = __float2half_rn(f0.z); h[3] = __float2half_rn(f0.w);
        h[4] = __float2half_rn(f1.x); h[5] = __float2half_rn(f1.y);
        h[6] = __float2half_rn(f1.z); h[7] = __float2half_rn(f1.w);
        *(uint4*)(Xh + base) = *(uint4*)h;
    } else {
        int i = (b - 256) * 2048 + threadIdx.x * 8;   // index into Wf [256*384]
        if (i < 256 * 384) {
            int k = i / 384, c = i % 384;
            __half h[8];
            #pragma unroll
            for (int q = 0; q < 8; q++) {
                int cc = c + q;
                float v = (cc < 128) ? W1[k * 128 + cc] : W2[k * 256 + (cc - 128)];
                h[q] = __float2half_rn(v);
            }
            *(uint4*)(Wf + i) = *(uint4*)h;
        }
    }
}

// a1[z][row][col8..+8] *= cinv1[z][row]  (in place)
__global__ void scale_a1_k(__half* __restrict__ a1, const float* __restrict__ cinv1) {
    int c8 = threadIdx.x * 8;
    int row = blockIdx.y, z = blockIdx.z;
    size_t i = (size_t)z * NN + (size_t)row * N + c8;
    float sc = cinv1[z * N + row];
    uint4 raw = *(uint4*)(a1 + i);
    __half2* h = (__half2*)&raw;
    #pragma unroll
    for (int q = 0; q < 4; q++) {
        float2 f = __half22float2(h[q]);
        h[q] = __floats2half2_rn(f.x * sc, f.y * sc);
    }
    *(uint4*)(a1 + i) = raw;
}

// column partial sums over 32-row chunks, 8 cols per thread (uint4 loads)
__global__ void colsum_part_h(const __half* __restrict__ H, float* __restrict__ part, size_t sH) {
    int c8 = threadIdx.x * 8;
    const __half* p = H + (size_t)blockIdx.z * sH + (size_t)blockIdx.y * 32 * N + c8;
    float s[8] = {};
    #pragma unroll 4
    for (int i = 0; i < 32; i++) {
        uint4 raw = *(const uint4*)(p + (size_t)i * N);
        const __half2* h = (const __half2*)&raw;
        #pragma unroll
        for (int q = 0; q < 4; q++) {
            float2 f = __half22float2(h[q]);
            s[q * 2] += f.x; s[q * 2 + 1] += f.y;
        }
    }
    float* dst = part + ((size_t)blockIdx.z * 64 + blockIdx.y) * N + c8;
    *(float4*)dst = make_float4(s[0], s[1], s[2], s[3]);
    *(float4*)(dst + 4) = make_float4(s[4], s[5], s[6], s[7]);
}

__global__ void cinv_fin_k(const float* __restrict__ part, float* __restrict__ cinv) {
    int col = blockIdx.x * 256 + threadIdx.x;
    int z = blockIdx.z;
    float s = 0.f;
    #pragma unroll
    for (int r = 0; r < 64; r++) s += part[((size_t)z * 64 + r) * N + col];
    cinv[z * N + col] = (s == 0.f) ? 0.f : 1.f / s;
}

__global__ void fin2_k(const float* __restrict__ part, float* __restrict__ cinv2,
                       float* __restrict__ cinvs) {
    int col = blockIdx.x * 256 + threadIdx.x;
    float sz[2];
    #pragma unroll
    for (int z = 0; z < 2; z++) {
        float s = 0.f;
        #pragma unroll
        for (int r = 0; r < 64; r++) s += part[((size_t)z * 64 + r) * N + col];
        sz[z] = s;
        cinv2[z * N + col] = (s == 0.f) ? 0.f : 1.f / s;
    }
    float d = sz[0] + sz[1] - 1.f;
    cinvs[col] = (d == 0.f) ? 0.f : 1.f / d;
}

__global__ void y_k(const float* __restrict__ Xo, const float* __restrict__ lw,
                    const float* __restrict__ lb, const int* __restrict__ txp,
                    float* __restrict__ outy) {
    int id = blockIdx.x * blockDim.x + threadIdx.x;
    if (id >= NT * NUM_CLASS) return;
    int t = id / NUM_CLASS, k = id % NUM_CLASS;
    const float* xr = Xo + (size_t)txp[t] * 384;
    const float* wr = lw + (size_t)k * W_OUT;
    float s = 0.f;
    #pragma unroll 4
    for (int d = 0; d < W_OUT; d++) s = fmaf(xr[d], wr[d], s);
    outy[id] = s + lb[k];
}

__global__ void lossC_k(const float* __restrict__ y, const int* __restrict__ tgt,
                        float* __restrict__ part) {
    __shared__ float red[256];
    int t = blockIdx.x * 256 + threadIdx.x;
    float yv[NUM_CLASS];
    float m = -1e30f;
    #pragma unroll
    for (int k = 0; k < NUM_CLASS; k++) { yv[k] = y[t * NUM_CLASS + k]; m = fmaxf(m, yv[k]); }
    float se = 0.f;
    #pragma unroll
    for (int k = 0; k < NUM_CLASS; k++) se += expf(yv[k] - m);
    float lse = m + logf(se);
    red[threadIdx.x] = yv[tgt[t]] - lse;
    __syncthreads();
    for (int s = 128; s > 0; s >>= 1) {
        if (threadIdx.x < s) red[threadIdx.x] += red[threadIdx.x + s];
        __syncthreads();
    }
    if (threadIdx.x == 0) part[blockIdx.x] = red[0];
}

__global__ void lossR_k(const float* __restrict__ XORb, const float* __restrict__ X,
                        float* __restrict__ part) {
    __shared__ float red[256];
    const size_t total = (size_t)N * W_IN;
    size_t tid = (size_t)blockIdx.x * 256 + threadIdx.x;
    size_t stride = (size_t)gridDim.x * 256;
    float acc = 0.f;
    for (size_t i = tid; i < total; i += stride) {
        size_t row = i >> 8, col = i & 255;
        float x = XORb[row * 384 + 128 + col];
        if (x > 1.f || x < 0.f) x = 1.f / (1.f + expf(-x));
        float p = fminf(fmaxf(x, 1e-7f), 1.f - 1e-7f);
        float t = X[i];
        acc += t * logf(p) + (1.f - t) * log1pf(-p);
    }
    red[threadIdx.x] = acc;
    __syncthreads();
    for (int s = 128; s > 0; s >>= 1) {
        if (threadIdx.x < s) red[threadIdx.x] += red[threadIdx.x + s];
        __syncthreads();
    }
    if (threadIdx.x == 0) part[blockIdx.x] = red[0];
}

__global__ void final_k(const float* __restrict__ partR, const float* __restrict__ partC,
                        float* __restrict__ out) {
    __shared__ float red[256];
    red[threadIdx.x] = partR[threadIdx.x] + partR[threadIdx.x + 256];
    __syncthreads();
    for (int s = 128; s > 0; s >>= 1) {
        if (threadIdx.x < s) red[threadIdx.x] += red[threadIdx.x + s];
        __syncthreads();
    }
    if (threadIdx.x == 0) {
        float lossR = -red[0] / (float)((size_t)N * W_IN);
        float sC = partC[0] + partC[1] + partC[2] + partC[3];
        float lossC = -sC / (float)NT;
        out[0] = lossC + lossR;
        out[1 + NT * NUM_CLASS + 3 * C * E] = lossR;
    }
}

// ============================ host side ============================
constexpr int SMEM_NT = (128 * 72 + 64 * 136) * 2 * 3;   // 107520
constexpr int SMEM_TA = (64 * 136 + 64 * 136) * 2 * 3;   // 104448

extern "C" void kernel_launch(void* const* d_in, const int* in_sizes, int n_in,
                              void* d_out, int out_size) {
    __half* Hh = nullptr;
    float* S = nullptr;
    cudaGetSymbolAddress((void**)&Hh, g_h);
    cudaGetSymbolAddress((void**)&S, g_f);

    const float* A   = (const float*)d_in[0];
    const float* X   = (const float*)d_in[1];
    const float* W   = (const float*)d_in[2];
    const float* W1  = (const float*)d_in[3];
    const float* W2  = (const float*)d_in[4];
    const float* lw  = (const float*)d_in[5];
    const float* lb  = (const float*)d_in[6];
    const float* w0a = (const float*)d_in[7];
    const float* w0b = (const float*)d_in[8];
    const float* w1a = (const float*)d_in[9];
    const int* txp   = (const int*)d_in[10];
    const int* tgt   = (const int*)d_in[11];
    float* out = (float*)d_out;

    cudaFuncSetAttribute((const void*)hgemm_k<false, false>,
                         cudaFuncAttributeMaxDynamicSharedMemorySize, SMEM_NT);
    cudaFuncSetAttribute((const void*)hgemm_k<true, false>,
                         cudaFuncAttributeMaxDynamicSharedMemorySize, SMEM_TA);
    cudaFuncSetAttribute((const void*)hgemm_k<true, true>,
                         cudaFuncAttributeMaxDynamicSharedMemorySize, SMEM_TA);

    // 1. softmax weights + Ws outputs; X/W1/W2 -> fp16
    softmax_init_k<<<1, 32>>>(w0a, w0b, w1a, S + FO_SW, out);
    convh_k<<<304, 256>>>(X, W1, W2, Hh + HO_XH, Hh + HO_WF);
    // 2. a, b, a1 (fp16)
    gtconv_k<<<(unsigned)(NN / 4 / 256), 256>>>(A, S + FO_SW, Hh + HO_A, Hh + HO_B, Hh + HO_A1);
    // 3. H = a @ b, diag->0
    hgemm_k<false, false><<<dim3(16, 16, 2), 256, SMEM_NT>>>(
        Hh + HO_A, Hh + HO_B, Hh + HO_H, N, N, N, N, NN, NN, NN, 0, nullptr, 0, 2,
        1, nullptr, 0, 0);
    // 4. cinv1 = 1/colsum(H)
    colsum_part_h<<<dim3(1, 64, 2), 256>>>(Hh + HO_H, S + FO_COLP, NN);
    cinv_fin_k<<<dim3(8, 1, 2), 256>>>(S + FO_COLP, S + FO_CI1);
    // 5. a1 <- diag(cinv1) @ a1  (in place)
    scale_a1_k<<<dim3(1, N, 2), 256>>>(Hh + HO_A1, S + FO_CI1);
    // 6. H2 = H @ a1n, diag->1
    hgemm_k<false, false><<<dim3(16, 16, 2), 256, SMEM_NT>>>(
        Hh + HO_H, Hh + HO_A1, Hh + HO_H2, N, N, N, N, NN, NN, NN, 0, nullptr, 0, 4,
        1, nullptr, 0, 0);
    // 7. cinv2, cinvs from H2 colsums  (cinvs = 1/(s0+s1-1))
    colsum_part_h<<<dim3(1, 64, 2), 256>>>(Hh + HO_H2, S + FO_COLP, NN);
    fin2_k<<<8, 256>>>(S + FO_COLP, S + FO_CI2, S + FO_CIS);
    // 8. XW = Xh @ Wh  (tensor, W converted inline below via Wf? no — use W directly)
    //    XW = Xh @ W(half): W is f32; use Xh @ W via Wf? W is separate; convert W on the fly:
    //    reuse hgemm with B = fp16 W — we convert W into HO_XW region? Simplest: W as f32 is
    //    only 128KB; convert inside convh? Instead: XW = Xh @ Wh where Wh shares Wf? Wf holds W1|W2.
    //    Use a dedicated small conversion region: reuse HO_XCAT (not yet written) for Wh [256][128].
    {
        // convert W (f32 [256,128]) to half into HO_XCAT temp (overwritten later by comb9)
        // done by convh-style inline kernel:
    }
    // W -> half (temp at HO_XCAT, 32768 halves)
    {
        struct L { static void launch(const float* W, __half* Wh) {} };
    }
    // (see convW_k below)
    extern __global__ void convW_k(const float*, __half*);
    convW_k<<<16, 256>>>(W, Hh + HO_XCAT);
    hgemm_k<false, false><<<dim3(1, 16, 1), 256, SMEM_NT>>>(
        Hh + HO_XH, Hh + HO_XCAT, Hh + HO_XW, 256, 256, 128, 128, 0, 0, 0, 0,
        nullptr, 0, 0, 1, nullptr, 0, 0);
    // 9. P[z*2+s] = (H2[z]^T @ XW) k-split partials; combine -> Xcat
    hgemm_k<true, false><<<dim3(1, 16, 4), 256, SMEM_TA>>>(
        Hh + HO_H2, Hh + HO_XW, nullptr, N, N, 128, 0, NN, 0, 0, 0, nullptr, 0, 0,
        2, S + FO_P, 128, (size_t)N * 128);
    comb9_k<<<dim3(N, 2), 128>>>(S + FO_P, S + FO_CI2, Hh + HO_XCAT);
    // 10. Xcw = Xcat @ [W1|W2]  (tensor)
    hgemm_k<false, false><<<dim3(3, 16, 1), 256, SMEM_NT>>>(
        Hh + HO_XCAT, Hh + HO_WF, Hh + HO_XCW, 256, 256, 384, 384, 0, 0, 0, 0,
        nullptr, 0, 0, 1, nullptr, 0, 0);
    // 11. P[s] = partial sums of (sum_z H2[z]^T @ Xcw); combine -> Xor (f32)
    hgemm_k<true, true><<<dim3(3, 16, 4), 256, SMEM_TA>>>(
        Hh + HO_H2, Hh + HO_XCW, nullptr, N, N, 384, 0, NN, 0, 0, 0, nullptr, 0, 0,
        4, S + FO_P, 384, (size_t)N * 384);
    comb11_k<<<dim3(N, 3), 128>>>(S + FO_P, Hh + HO_XCW, S + FO_CIS, S + FO_XOR);
    // 12. y, losses, final
    y_k<<<(NT * NUM_CLASS) / 256, 256>>>(S + FO_XOR, lw, lb, txp, out + 1);
    lossC_k<<<NT / 256, 256>>>(out + 1, tgt, S + FO_PC);
    lossR_k<<<512, 256>>>(S + FO_XOR, X, S + FO_PR);
    final_k<<<1, 256>>>(S + FO_PR, S + FO_PC, out);
}

// W (f32 [256,128]) -> half
__global__ void convW_k(const float* __restrict__ W, __half* __restrict__ Wh) {
    int i = blockIdx.x * 2048 + threadIdx.x * 8;
    const float4* src = (const float4*)(W + i);
    __half h[8];
    float4 f0 = src[0], f1 = src[1];
    h[0] = __float2half_rn(f0.x); h[1] = __float2half_rn(f0.y);
    h[2] = __float2half_rn(f0.z); h[3] = __float2half_rn(f0.w);
    h[4] = __float2half_rn(f1.x); h[5] = __float2half_rn(f1.y);
    h[6] = __float2half_rn(f1.z); h[7] = __float2half_rn(f1.w);
    *(uint4*)(Wh + i) = *(uint4*)h;
}